// round 13
// baseline (speedup 1.0000x reference)
#include <cuda_runtime.h>
#include <cuda_bf16.h>
#include <math.h>
#include <stdint.h>

// Problem constants
#define B_      2
#define N_      2048
#define DIM_    1024
#define H_      16
#define DH_     64
#define M_      512
#define INNER_  1024
#define KV_     2561      // M + 1 + N
#define NXL_    2049      // 1 + N
#define KVP_    2624      // KV padded to 41*64

// ---------------------------------------------------------------------------
// Device scratch
// ---------------------------------------------------------------------------
__device__ __align__(16) float g_q   [(size_t)B_ * N_ * INNER_];

__device__ unsigned g_maxbits[2];   // [0] = max|x|, [1] = max|Wq,Wkv|

// int8 2-term operands for fused qkv projection
__device__ __align__(256) int8_t g_xi1[(size_t)B_ * N_ * DIM_];
__device__ __align__(256) int8_t g_xi0[(size_t)B_ * N_ * DIM_];
__device__ __align__(256) int8_t g_wi1[(size_t)3072 * 1024];
__device__ __align__(256) int8_t g_wi0[(size_t)3072 * 1024];

// bf16 operands for out projection
__device__ __align__(256) __nv_bfloat16 g_ah[(size_t)B_ * N_ * INNER_];
__device__ __align__(256) __nv_bfloat16 g_al[(size_t)B_ * N_ * INNER_];
__device__ __align__(256) __nv_bfloat16 g_wh[(size_t)1024 * 1024];
__device__ __align__(256) __nv_bfloat16 g_wl[(size_t)1024 * 1024];

// attention operands, bf16 hi/lo
__device__ __align__(256) __nv_bfloat16 g_qbh[(size_t)B_ * H_ * N_ * DH_];
__device__ __align__(256) __nv_bfloat16 g_qbl[(size_t)B_ * H_ * N_ * DH_];
__device__ __align__(256) __nv_bfloat16 g_kbh[(size_t)B_ * H_ * KVP_ * DH_];
__device__ __align__(256) __nv_bfloat16 g_kbl[(size_t)B_ * H_ * KVP_ * DH_];
__device__ __align__(256) __nv_bfloat16 g_vth[(size_t)B_ * H_ * DH_ * KVP_];
__device__ __align__(256) __nv_bfloat16 g_vtl[(size_t)B_ * H_ * DH_ * KVP_];

// ---------------------------------------------------------------------------
// PTX helpers — base sm_103-safe subset
// ---------------------------------------------------------------------------
__device__ __forceinline__ uint32_t smem_u32(const void* p) {
    uint32_t a;
    asm("{ .reg .u64 t; cvta.to.shared.u64 t, %1; cvt.u32.u64 %0, t; }" : "=r"(a) : "l"(p));
    return a;
}

#define CP_ASYNC16(smem, gptr) \
    asm volatile("cp.async.cg.shared.global [%0], [%1], 16;" :: "r"(smem), "l"(gptr) : "memory")
#define CP_COMMIT() asm volatile("cp.async.commit_group;" ::: "memory")
#define CP_WAIT0()  asm volatile("cp.async.wait_group 0;" ::: "memory")
#define CP_WAIT1()  asm volatile("cp.async.wait_group 1;" ::: "memory")

__device__ __forceinline__ void ldmx4(uint32_t& r0, uint32_t& r1, uint32_t& r2, uint32_t& r3,
                                      uint32_t addr) {
    asm volatile("ldmatrix.sync.aligned.m8n8.x4.shared.b16 {%0,%1,%2,%3}, [%4];"
                 : "=r"(r0), "=r"(r1), "=r"(r2), "=r"(r3) : "r"(addr));
}

__device__ __forceinline__ void mma_bf16(float* c, const uint32_t* a, const uint32_t* b) {
    asm volatile(
        "mma.sync.aligned.m16n8k16.row.col.f32.bf16.bf16.f32 "
        "{%0,%1,%2,%3}, {%4,%5,%6,%7}, {%8,%9}, {%0,%1,%2,%3};"
        : "+f"(c[0]), "+f"(c[1]), "+f"(c[2]), "+f"(c[3])
        : "r"(a[0]), "r"(a[1]), "r"(a[2]), "r"(a[3]), "r"(b[0]), "r"(b[1]));
}

__device__ __forceinline__ void mma_s8(int* c, const uint32_t* a, const uint32_t* b) {
    asm volatile(
        "mma.sync.aligned.m16n8k32.row.col.s32.s8.s8.s32 "
        "{%0,%1,%2,%3}, {%4,%5,%6,%7}, {%8,%9}, {%0,%1,%2,%3};"
        : "+r"(c[0]), "+r"(c[1]), "+r"(c[2]), "+r"(c[3])
        : "r"(a[0]), "r"(a[1]), "r"(a[2]), "r"(a[3]), "r"(b[0]), "r"(b[1]));
}

// exp2 without MUFU (attention domain x <= 0)
__device__ __forceinline__ float exp2fast(float x) {
    x = fmaxf(x, -126.0f);
    float t = x + 12582912.0f;
    int k = __float_as_int(t) - 0x4b400000;
    float f = x - (t - 12582912.0f);
    float p = 1.3333558e-3f;
    p = fmaf(p, f, 9.6181291e-3f);
    p = fmaf(p, f, 5.5504109e-2f);
    p = fmaf(p, f, 2.4022651e-1f);
    p = fmaf(p, f, 6.9314718e-1f);
    p = fmaf(p, f, 1.0f);
    return __int_as_float(__float_as_int(p) + (k << 23));
}

__device__ __forceinline__ uint32_t packbf2(float a, float b) {
    __nv_bfloat162 t = __floats2bfloat162_rn(a, b);
    return *(uint32_t*)&t;
}

// ---------------------------------------------------------------------------
// absmax over x and Wq/Wkv (atomicMax on positive-float bit patterns)
// ---------------------------------------------------------------------------
__global__ void absmax_xw(const float* __restrict__ x,
                          const float* __restrict__ wq,
                          const float* __restrict__ wkv)
{
    const size_t NX = (size_t)B_ * N_ * DIM_;
    const size_t NWQ = (size_t)1024 * 1024;
    const size_t NWK = (size_t)1024 * 2048;
    size_t gid = (size_t)blockIdx.x * blockDim.x + threadIdx.x;
    size_t stride = (size_t)gridDim.x * blockDim.x;

    float mx = 0.f, mw = 0.f;
    for (size_t i = gid; i < NX / 4; i += stride) {
        float4 v = ((const float4*)x)[i];
        mx = fmaxf(mx, fmaxf(fmaxf(fabsf(v.x), fabsf(v.y)), fmaxf(fabsf(v.z), fabsf(v.w))));
    }
    for (size_t i = gid; i < NWQ / 4; i += stride) {
        float4 v = ((const float4*)wq)[i];
        mw = fmaxf(mw, fmaxf(fmaxf(fabsf(v.x), fabsf(v.y)), fmaxf(fabsf(v.z), fabsf(v.w))));
    }
    for (size_t i = gid; i < NWK / 4; i += stride) {
        float4 v = ((const float4*)wkv)[i];
        mw = fmaxf(mw, fmaxf(fmaxf(fabsf(v.x), fabsf(v.y)), fmaxf(fabsf(v.z), fabsf(v.w))));
    }
#pragma unroll
    for (int off = 16; off; off >>= 1) {
        mx = fmaxf(mx, __shfl_xor_sync(0xffffffffu, mx, off));
        mw = fmaxf(mw, __shfl_xor_sync(0xffffffffu, mw, off));
    }
    if ((threadIdx.x & 31) == 0) {
        atomicMax(&g_maxbits[0], __float_as_uint(mx));
        atomicMax(&g_maxbits[1], __float_as_uint(mw));
    }
}

// quantize helper: i = round(v*inv), clamp; hi = radix-128 digit, lo = residue
__device__ __forceinline__ void quant2(float v, float inv, int& hi, int& lo) {
    int i = __float2int_rn(v * inv);
    i = max(-16255, min(16255, i));
    hi = (i + 64) >> 7;
    lo = i - (hi << 7);
}

// ---------------------------------------------------------------------------
// quantize x -> xi1/xi0 (layout preserved, [row][1024])
// ---------------------------------------------------------------------------
__global__ void quantize_x(const float* __restrict__ in)
{
    size_t i = (size_t)blockIdx.x * blockDim.x + threadIdx.x;
    const size_t n4 = (size_t)B_ * N_ * DIM_ / 4;
    if (i >= n4) return;
    float inv = 16200.0f / __uint_as_float(g_maxbits[0]);
    float4 v = ((const float4*)in)[i];
    int h0, l0, h1, l1, h2, l2, h3, l3;
    quant2(v.x, inv, h0, l0);
    quant2(v.y, inv, h1, l1);
    quant2(v.z, inv, h2, l2);
    quant2(v.w, inv, h3, l3);
    uint32_t ph = (uint32_t)(h0 & 255) | ((uint32_t)(h1 & 255) << 8)
                | ((uint32_t)(h2 & 255) << 16) | ((uint32_t)(h3 & 255) << 24);
    uint32_t pl = (uint32_t)(l0 & 255) | ((uint32_t)(l1 & 255) << 8)
                | ((uint32_t)(l2 & 255) << 16) | ((uint32_t)(l3 & 255) << 24);
    ((uint32_t*)g_xi1)[i] = ph;
    ((uint32_t*)g_xi0)[i] = pl;
}

// ---------------------------------------------------------------------------
// Weight transpose + int8 quantize: bx<32 -> Wq (rows 0..1023 of wT),
// bx>=32 -> Wkv (rows 1024..3071). Output wT [n][1024] int8 hi/lo.
// ---------------------------------------------------------------------------
__global__ void transpose_quant_w(const float* __restrict__ Wq,
                                  const float* __restrict__ Wkv)
{
    __shared__ float s[32][33];
    int bx = blockIdx.x;
    const float* in;
    int Ncols, n0, obase;
    if (bx < 32) { in = Wq;  Ncols = 1024; n0 = bx * 32;        obase = 0; }
    else         { in = Wkv; Ncols = 2048; n0 = (bx - 32) * 32; obase = 1024; }
    int k0 = blockIdx.y * 32;
    int tx = threadIdx.x, ty = threadIdx.y;  // 32 x 8
    float inv = 16200.0f / __uint_as_float(g_maxbits[1]);
#pragma unroll
    for (int r = 0; r < 4; r++)
        s[ty + r * 8][tx] = in[(size_t)(k0 + ty + r * 8) * Ncols + n0 + tx];
    __syncthreads();
#pragma unroll
    for (int r = 0; r < 4; r++) {
        int row = ty + r * 8;
        float v = s[tx][row];
        int hi, lo;
        quant2(v, inv, hi, lo);
        size_t o = (size_t)(obase + n0 + row) * 1024 + k0 + tx;
        g_wi1[o] = (int8_t)hi;
        g_wi0[o] = (int8_t)lo;
    }
}

// Wout transpose + bf16 split (unchanged numerics)
__global__ void transpose_split(const float* __restrict__ in,
                                __nv_bfloat16* __restrict__ hi,
                                __nv_bfloat16* __restrict__ lo, int Ncols)
{
    __shared__ float s[32][33];
    int n0 = blockIdx.x * 32, k0 = blockIdx.y * 32;
    int tx = threadIdx.x, ty = threadIdx.y;
#pragma unroll
    for (int r = 0; r < 4; r++)
        s[ty + r * 8][tx] = in[(size_t)(k0 + ty + r * 8) * Ncols + n0 + tx];
    __syncthreads();
#pragma unroll
    for (int r = 0; r < 4; r++) {
        int row = ty + r * 8;
        float v = s[tx][row];
        __nv_bfloat16 h = __float2bfloat16(v);
        __nv_bfloat16 l = __float2bfloat16(v - __bfloat162float(h));
        size_t o = (size_t)(n0 + row) * 1024 + k0 + tx;
        hi[o] = h;
        lo[o] = l;
    }
}

// ---------------------------------------------------------------------------
// int8 GEMM (fused qkv): CTA 128x64, 128 threads (4 warps 2m x 2n),
// warp 64x32, BK=64 bytes, 2-stage cp.async, 2-term radix-128 split:
// C = s * (16384*accH + 128*accM); accH = A1B1, accM = A1B0 + A0B1.
// col<1024 -> g_q; col>=1024 -> out2 scatter (next_xl rows 1..N)
// ---------------------------------------------------------------------------
#define I8_STAGE 30720
#define I8_A1 0
#define I8_A0 10240
#define I8_B1 20480
#define I8_B0 25600
#define I8_SMEM (2 * I8_STAGE + 128)

__global__ __launch_bounds__(128, 2) void gemm_i8(
    float* __restrict__ outQ, float* __restrict__ out2)
{
    extern __shared__ char dsm[];
    const int tid = threadIdx.x;
    const int lane = tid & 31;
    const int wid = tid >> 5;
    const int bm = blockIdx.y * 128, bn = blockIdx.x * 64;
    const int warpM = (wid >> 1) * 64;   // 0, 64
    const int warpN = (wid & 1) * 32;    // 0, 32

    uint32_t sb = (smem_u32(dsm) + 127) & ~127u;

    auto load_stage = [&](int chunk, int stage) {
        const int k0 = chunk * 64;
        uint32_t base = sb + stage * I8_STAGE;
#pragma unroll
        for (int e = 0; e < 12; e++) {
            int lin = e * 128 + tid;    // 0..1535
            uint32_t soff;
            const int8_t* gp;
            if (lin < 512) {                 // A1: 128 rows x 4 16B chunks
                int r = lin >> 2, c = lin & 3;
                soff = I8_A1 + (uint32_t)r * 80u + (uint32_t)c * 16u;
                gp = g_xi1 + (size_t)(bm + r) * 1024 + k0 + c * 16;
            } else if (lin < 1024) {         // A0
                int idx = lin - 512;
                int r = idx >> 2, c = idx & 3;
                soff = I8_A0 + (uint32_t)r * 80u + (uint32_t)c * 16u;
                gp = g_xi0 + (size_t)(bm + r) * 1024 + k0 + c * 16;
            } else if (lin < 1280) {         // B1: 64 rows x 4
                int idx = lin - 1024;
                int r = idx >> 2, c = idx & 3;
                soff = I8_B1 + (uint32_t)r * 80u + (uint32_t)c * 16u;
                gp = g_wi1 + (size_t)(bn + r) * 1024 + k0 + c * 16;
            } else {                         // B0
                int idx = lin - 1280;
                int r = idx >> 2, c = idx & 3;
                soff = I8_B0 + (uint32_t)r * 80u + (uint32_t)c * 16u;
                gp = g_wi0 + (size_t)(bn + r) * 1024 + k0 + c * 16;
            }
            CP_ASYNC16(base + soff, gp);
        }
        CP_COMMIT();
    };

    int accH[4][4][4], accM[4][4][4];
#pragma unroll
    for (int i = 0; i < 4; i++)
#pragma unroll
        for (int j = 0; j < 4; j++)
#pragma unroll
            for (int k = 0; k < 4; k++) { accH[i][j][k] = 0; accM[i][j][k] = 0; }

    load_stage(0, 0);

    const int NC = 16;   // 1024 / 64
    for (int ch = 0; ch < NC; ch++) {
        int s = ch & 1;
        if (ch + 1 < NC) { load_stage(ch + 1, s ^ 1); CP_WAIT1(); }
        else             { CP_WAIT0(); }
        __syncthreads();

        uint32_t st = sb + s * I8_STAGE;
        uint32_t a1 = st + I8_A1, a0 = st + I8_A0, b1 = st + I8_B1, b0 = st + I8_B0;

#pragma unroll
        for (int kk = 0; kk < 2; kk++) {
            // koff selects a 32-byte k-slice (same addressing as bf16 16-elem slice)
            uint32_t koff = (uint32_t)kk * 32u + (uint32_t)(lane >> 4) * 16u;
            uint32_t b1f[4][2], b0f[4][2];
#pragma unroll
            for (int p = 0; p < 2; p++) {
                uint32_t off = (uint32_t)(warpN + p * 16 + (lane & 15)) * 80u + koff;
                uint32_t r0, r1, r2, r3;
                ldmx4(r0, r1, r2, r3, b1 + off);
                b1f[p * 2][0] = r0; b1f[p * 2 + 1][0] = r1;
                b1f[p * 2][1] = r2; b1f[p * 2 + 1][1] = r3;
                ldmx4(r0, r1, r2, r3, b0 + off);
                b0f[p * 2][0] = r0; b0f[p * 2 + 1][0] = r1;
                b0f[p * 2][1] = r2; b0f[p * 2 + 1][1] = r3;
            }
#pragma unroll
            for (int fm = 0; fm < 4; fm++) {
                uint32_t off = (uint32_t)(warpM + fm * 16 + (lane & 15)) * 80u + koff;
                uint32_t a1f[4], a0f[4];
                ldmx4(a1f[0], a1f[1], a1f[2], a1f[3], a1 + off);
                ldmx4(a0f[0], a0f[1], a0f[2], a0f[3], a0 + off);
#pragma unroll
                for (int fn = 0; fn < 4; fn++) {
                    mma_s8(accH[fm][fn], a1f, b1f[fn]);
                    mma_s8(accM[fm][fn], a1f, b0f[fn]);
                    mma_s8(accM[fm][fn], a0f, b1f[fn]);
                }
            }
        }
        __syncthreads();
    }

    const float sX = __uint_as_float(g_maxbits[0]) * (1.0f / 16200.0f);
    const float sW = __uint_as_float(g_maxbits[1]) * (1.0f / 16200.0f);
    const float sc = sX * sW;

    const int gr = lane >> 2;
    const int gc = (lane & 3) * 2;
#pragma unroll
    for (int fm = 0; fm < 4; fm++) {
#pragma unroll
        for (int fn = 0; fn < 4; fn++) {
            int row0 = bm + warpM + fm * 16 + gr;
            int col  = bn + warpN + fn * 8 + gc;
#pragma unroll
            for (int half = 0; half < 2; half++) {
                int rr = row0 + half * 8;
                float v0 = sc * (16384.f * (float)accH[fm][fn][2 * half]
                                 + 128.f * (float)accM[fm][fn][2 * half]);
                float v1 = sc * (16384.f * (float)accH[fm][fn][2 * half + 1]
                                 + 128.f * (float)accM[fm][fn][2 * half + 1]);
                if (col < 1024) {
                    *(float2*)&outQ[(size_t)rr * 1024 + col] = make_float2(v0, v1);
                } else {
                    int ckv = col - 1024;
                    int s = ckv >> 10;
                    int hh = (ckv & 1023) >> 6;
                    int d = ckv & 63;
                    int b = rr >> 11;
                    int n = rr & 2047;
                    size_t o = ((((size_t)s * B_ + b) * H_ + hh) * NXL_ + n + 1) * 64 + d;
                    *(float2*)&out2[o] = make_float2(v0, v1);
                }
            }
        }
    }
}

// ---------------------------------------------------------------------------
// bf16 GEMM for out-projection (proven R7/R12 config, mode1 only)
// ---------------------------------------------------------------------------
#define STAGE_BYTES 40960
#define GEMM_SMEM   (2 * STAGE_BYTES + 128)

__global__ __launch_bounds__(256, 2) void gemm_mma3(
    const __nv_bfloat16* __restrict__ Ah, const __nv_bfloat16* __restrict__ Al,
    const __nv_bfloat16* __restrict__ Bh, const __nv_bfloat16* __restrict__ Bl,
    float* __restrict__ outC)
{
    extern __shared__ char dsm[];
    const int tid = threadIdx.x;
    const int lane = tid & 31;
    const int wid = tid >> 5;
    const int bm = blockIdx.y * 128, bn = blockIdx.x * 128;
    const int warpM = (wid >> 2) * 64;
    const int warpN = (wid & 3) * 32;

    uint32_t sb = (smem_u32(dsm) + 127) & ~127u;

    auto load_stage = [&](int chunk, int stage) {
        const int k0 = chunk * 32;
        uint32_t base = sb + stage * STAGE_BYTES;
#pragma unroll
        for (int e = 0; e < 8; e++) {
            int lin = e * 256 + tid;
            int buf = lin >> 9;
            int idx = lin & 511;
            int r = idx >> 2;
            int c = idx & 3;
            uint32_t soff = (uint32_t)buf * 10240u + (uint32_t)r * 80u + (uint32_t)c * 16u;
            const __nv_bfloat16* gp;
            if (buf == 0)      gp = Ah + (size_t)(bm + r) * 1024 + k0;
            else if (buf == 1) gp = Al + (size_t)(bm + r) * 1024 + k0;
            else if (buf == 2) gp = Bh + (size_t)(bn + r) * 1024 + k0;
            else               gp = Bl + (size_t)(bn + r) * 1024 + k0;
            CP_ASYNC16(base + soff, gp + c * 8);
        }
        CP_COMMIT();
    };

    float acc[4][4][4];
#pragma unroll
    for (int i = 0; i < 4; i++)
#pragma unroll
        for (int j = 0; j < 4; j++)
#pragma unroll
            for (int k = 0; k < 4; k++) acc[i][j][k] = 0.f;

    load_stage(0, 0);

    const int NC = 32;
    for (int ch = 0; ch < NC; ch++) {
        int s = ch & 1;
        if (ch + 1 < NC) { load_stage(ch + 1, s ^ 1); CP_WAIT1(); }
        else             { CP_WAIT0(); }
        __syncthreads();

        uint32_t st = sb + s * STAGE_BYTES;
        uint32_t aH = st, aL = st + 10240, bH = st + 20480, bL = st + 30720;

#pragma unroll
        for (int kk = 0; kk < 2; kk++) {
            uint32_t bh[4][2], bl[4][2];
#pragma unroll
            for (int p = 0; p < 2; p++) {
                uint32_t off = (uint32_t)(warpN + p * 16 + (lane & 15)) * 80u
                             + (uint32_t)kk * 32u + (uint32_t)(lane >> 4) * 16u;
                uint32_t r0, r1, r2, r3;
                ldmx4(r0, r1, r2, r3, bH + off);
                bh[p * 2][0] = r0; bh[p * 2 + 1][0] = r1;
                bh[p * 2][1] = r2; bh[p * 2 + 1][1] = r3;
                ldmx4(r0, r1, r2, r3, bL + off);
                bl[p * 2][0] = r0; bl[p * 2 + 1][0] = r1;
                bl[p * 2][1] = r2; bl[p * 2 + 1][1] = r3;
            }
#pragma unroll
            for (int fm = 0; fm < 4; fm++) {
                uint32_t off = (uint32_t)(warpM + fm * 16 + (lane & 15)) * 80u
                             + (uint32_t)kk * 32u + (uint32_t)(lane >> 4) * 16u;
                uint32_t ah[4], al[4];
                ldmx4(ah[0], ah[1], ah[2], ah[3], aH + off);
                ldmx4(al[0], al[1], al[2], al[3], aL + off);
#pragma unroll
                for (int fn = 0; fn < 4; fn++) {
                    mma_bf16(acc[fm][fn], ah, bh[fn]);
                    mma_bf16(acc[fm][fn], ah, bl[fn]);
                    mma_bf16(acc[fm][fn], al, bh[fn]);
                }
            }
        }
        __syncthreads();
    }

    const int gr = lane >> 2;
    const int gc = (lane & 3) * 2;
#pragma unroll
    for (int fm = 0; fm < 4; fm++) {
#pragma unroll
        for (int fn = 0; fn < 4; fn++) {
            int row0 = bm + warpM + fm * 16 + gr;
            int col  = bn + warpN + fn * 8 + gc;
#pragma unroll
            for (int half = 0; half < 2; half++) {
                int rr = row0 + half * 8;
                *(float2*)&outC[(size_t)rr * 1024 + col] =
                    make_float2(acc[fm][fn][2 * half], acc[fm][fn][2 * half + 1]);
            }
        }
    }
}

// ---------------------------------------------------------------------------
// Q conversion: rotary + scale*log2(e), bf16 hi/lo, layout (b,h,i,d)
// ---------------------------------------------------------------------------
__global__ void convert_q_rot(const float* __restrict__ rotq)
{
    const int i0 = blockIdx.x * 64;
    const int h = blockIdx.y, b = blockIdx.z;
    const int tid = threadIdx.x;
    const size_t bh = (size_t)b * H_ + h;
    const float F = 0.18033688011112042f;
#pragma unroll
    for (int e = 0; e < 16; e++) {
        int idx = e * 256 + tid;
        int i = i0 + (idx >> 6);
        int d = idx & 63;
        int d2 = d ^ 32;
        const float* qrow = &g_q[((size_t)b * N_ + i) * INNER_ + h * DH_];
        float q0 = qrow[d], q1 = qrow[d2];
        float pos = rotq[(size_t)i * DH_ + d];
        float qr = (q0 * cosf(pos) + ((d < 32) ? -q1 : q1) * sinf(pos)) * F;
        __nv_bfloat16 qh = __float2bfloat16(qr);
        __nv_bfloat16 ql = __float2bfloat16(qr - __bfloat162float(qh));
        size_t o = (bh * N_ + i) * DH_ + d;
        g_qbh[o] = qh;
        g_qbl[o] = ql;
    }
}

// ---------------------------------------------------------------------------
// Assemble K (rotated, (b,h,j,d)) and Vt ((b,h,d,j)); also out2 null row.
// Reads fresh k/v projections from out2.
// ---------------------------------------------------------------------------
__global__ void assemble_kv2(const float* __restrict__ xl,
                             const float* __restrict__ nullkv,
                             const float* __restrict__ rotk,
                             float* __restrict__ out2)
{
    __shared__ uint16_t svh[64][72], svl[64][72];
    const int j0 = blockIdx.x * 64;
    const int h = blockIdx.y, b = blockIdx.z;
    const int tid = threadIdx.x;
    const size_t bh = (size_t)b * H_ + h;

#pragma unroll
    for (int e = 0; e < 16; e++) {
        int idx = e * 256 + tid;
        int jl = idx >> 6;
        int j = j0 + jl;
        int d = idx & 63;
        int d2 = d ^ 32;

        float k0 = 0.f, k1 = 0.f, v0 = 0.f, pos = 0.f;
        if (j < M_) {
            size_t base = (((size_t)b * H_ + h) * M_ + j) * DH_;
            size_t voff = (size_t)B_ * H_ * M_ * DH_;
            k0 = xl[base + d];
            k1 = xl[base + d2];
            v0 = xl[voff + base + d];
            pos = rotk[(size_t)j * DH_ + d];
        } else if (j == M_) {
            k0 = nullkv[h * DH_ + d];
            k1 = nullkv[h * DH_ + d2];
            v0 = nullkv[H_ * DH_ + h * DH_ + d];
            pos = rotk[(size_t)j * DH_ + d];
            out2[(((size_t)0 * B_ + b) * H_ + h) * NXL_ * 64 + d] = k0;
            out2[(((size_t)1 * B_ + b) * H_ + h) * NXL_ * 64 + d] = v0;
        } else if (j < KV_) {
            int n = j - M_ - 1;
            size_t kbase = ((((size_t)0 * B_ + b) * H_ + h) * NXL_ + n + 1) * 64;
            size_t vbase = ((((size_t)1 * B_ + b) * H_ + h) * NXL_ + n + 1) * 64;
            k0 = out2[kbase + d];
            k1 = out2[kbase + d2];
            v0 = out2[vbase + d];
            pos = rotk[(size_t)j * DH_ + d];
        }
        float rot = (d < 32) ? -k1 : k1;
        float kr = k0 * cosf(pos) + rot * sinf(pos);

        __nv_bfloat16 kh = __float2bfloat16(kr);
        __nv_bfloat16 kl = __float2bfloat16(kr - __bfloat162float(kh));
        size_t ko = (bh * KVP_ + j) * DH_ + d;
        g_kbh[ko] = kh;
        g_kbl[ko] = kl;

        __nv_bfloat16 vh = __float2bfloat16(v0);
        __nv_bfloat16 vl = __float2bfloat16(v0 - __bfloat162float(vh));
        svh[d][jl] = __bfloat16_as_ushort(vh);
        svl[d][jl] = __bfloat16_as_ushort(vl);
    }
    __syncthreads();

#pragma unroll
    for (int e = 0; e < 8; e++) {
        int idx = e * 256 + tid;
        int d = idx >> 5;
        int jj = (idx & 31) * 2;
        uint32_t ph = (uint32_t)svh[d][jj] | ((uint32_t)svh[d][jj + 1] << 16);
        uint32_t pl = (uint32_t)svl[d][jj] | ((uint32_t)svl[d][jj + 1] << 16);
        size_t o = (bh * DH_ + d) * KVP_ + j0 + jj;
        *(uint32_t*)&g_vth[o] = ph;
        *(uint32_t*)&g_vtl[o] = pl;
    }
}

// ---------------------------------------------------------------------------
// Flash attention: mma.sync 3-term S, 3-term PV, fp32 l (proven numerics)
// ---------------------------------------------------------------------------
#define FL_BUF   9216
#define FL_SMEM  (10 * FL_BUF)

__global__ __launch_bounds__(128, 2) void flash2()
{
    extern __shared__ __align__(16) char fsm[];
    const int tid = threadIdx.x;
    const int lane = tid & 31;
    const int w = tid >> 5;
    const int bx = 31 - (int)blockIdx.x;
    const int h = blockIdx.y, b = blockIdx.z;
    const int i0 = bx * 64;
    const size_t bh = (size_t)b * H_ + h;

    uint32_t sb = smem_u32(fsm);

    {
        const __nv_bfloat16* q0 = g_qbh + (bh * N_ + i0) * DH_;
        const __nv_bfloat16* q1 = g_qbl + (bh * N_ + i0) * DH_;
#pragma unroll
        for (int e = 0; e < 8; e++) {
            int lin = e * 128 + tid;
            int buf = lin >> 9;
            int idx = lin & 511;
            int r = idx >> 3, c = idx & 7;
            const __nv_bfloat16* gp = (buf == 0 ? q0 : q1) + r * 64 + c * 8;
            CP_ASYNC16(sb + buf * FL_BUF + r * 144 + c * 16, gp);
        }
    }

    const __nv_bfloat16* kh0 = g_kbh + bh * KVP_ * DH_;
    const __nv_bfloat16* kl0 = g_kbl + bh * KVP_ * DH_;
    const __nv_bfloat16* vh0 = g_vth + bh * DH_ * KVP_;
    const __nv_bfloat16* vl0 = g_vtl + bh * DH_ * KVP_;

    auto load_kv = [&](int t, int s) {
        int j0 = t * 64;
        uint32_t base = sb + 2 * FL_BUF + s * (4 * FL_BUF);
#pragma unroll
        for (int e = 0; e < 16; e++) {
            int lin = e * 128 + tid;
            int buf = lin >> 9;
            int idx = lin & 511;
            int r = idx >> 3, c = idx & 7;
            const __nv_bfloat16* gp;
            if (buf == 0)      gp = kh0 + (size_t)(j0 + r) * 64 + c * 8;
            else if (buf == 1) gp = kl0 + (size_t)(j0 + r) * 64 + c * 8;
            else if (buf == 2) gp = vh0 + (size_t)r * KVP_ + j0 + c * 8;
            else               gp = vl0 + (size_t)r * KVP_ + j0 + c * 8;
            CP_ASYNC16(base + buf * FL_BUF + r * 144 + c * 16, gp);
        }
    };

    load_kv(0, 0);
    CP_COMMIT();

    const int rpart = ((lane >> 3) & 1) * 8 + (lane & 7);
    const int cpart = (lane >> 4) * 8;
    const int gr = lane >> 2;
    const int gc = (lane & 3) * 2;

    uint32_t qh[4][4], ql[4][4];
    float oAcc[8][4];
    float mrow[2] = {-1e30f, -1e30f};
    float lrow[2] = {0.f, 0.f};
#pragma unroll
    for (int fn = 0; fn < 8; fn++)
#pragma unroll
        for (int e = 0; e < 4; e++) oAcc[fn][e] = 0.f;

    const int ntiles = bx + 10;
    for (int t = 0; t < ntiles; t++) {
        if (t > 0) __syncthreads();
        if (t + 1 < ntiles) { load_kv(t + 1, (t + 1) & 1); CP_COMMIT(); CP_WAIT1(); }
        else                { CP_WAIT0(); }
        __syncthreads();

        if (t == 0) {
#pragma unroll
            for (int kk = 0; kk < 4; kk++) {
                uint32_t off = (uint32_t)(w * 16 + (lane & 15)) * 144u
                             + (uint32_t)(kk * 16 + cpart) * 2u;
                ldmx4(qh[kk][0], qh[kk][1], qh[kk][2], qh[kk][3], sb + off);
                ldmx4(ql[kk][0], ql[kk][1], ql[kk][2], ql[kk][3], sb + FL_BUF + off);
            }
        }

        uint32_t stK = sb + 2 * FL_BUF + (t & 1) * (4 * FL_BUF);
        uint32_t stV = stK + 2 * FL_BUF;

        float sAcc[8][4];
#pragma unroll
        for (int fn = 0; fn < 8; fn++)
#pragma unroll
            for (int e = 0; e < 4; e++) sAcc[fn][e] = 0.f;

#pragma unroll
        for (int kk = 0; kk < 4; kk++) {
#pragma unroll
            for (int p = 0; p < 4; p++) {
                uint32_t off = (uint32_t)(p * 16 + rpart) * 144u
                             + (uint32_t)(kk * 16 + cpart) * 2u;
                uint32_t h0, h1, h2, h3, l0, l1, l2, l3;
                ldmx4(h0, h1, h2, h3, stK + off);
                ldmx4(l0, l1, l2, l3, stK + FL_BUF + off);
                uint32_t bh0[2] = {h0, h2}, bh1[2] = {h1, h3};
                uint32_t bl0[2] = {l0, l2}, bl1[2] = {l1, l3};
                mma_bf16(sAcc[2 * p],     qh[kk], bh0);
                mma_bf16(sAcc[2 * p],     qh[kk], bl0);
                mma_bf16(sAcc[2 * p],     ql[kk], bh0);
                mma_bf16(sAcc[2 * p + 1], qh[kk], bh1);
                mma_bf16(sAcc[2 * p + 1], qh[kk], bl1);
                mma_bf16(sAcc[2 * p + 1], ql[kk], bh1);
            }
        }

        if (t >= ntiles - 2) {
            int j0 = t * 64;
#pragma unroll
            for (int fn = 0; fn < 8; fn++) {
#pragma unroll
                for (int e = 0; e < 4; e++) {
                    int gj = j0 + fn * 8 + gc + (e & 1);
                    int gi = i0 + w * 16 + gr + (e >> 1) * 8;
                    if (gj > gi + (KV_ - N_)) sAcc[fn][e] = -1e30f;
                }
            }
        }

        float mt0 = -1e30f, mt1 = -1e30f;
#pragma unroll
        for (int fn = 0; fn < 8; fn++) {
            mt0 = fmaxf(mt0, fmaxf(sAcc[fn][0], sAcc[fn][1]));
            mt1 = fmaxf(mt1, fmaxf(sAcc[fn][2], sAcc[fn][3]));
        }
        mt0 = fmaxf(mt0, __shfl_xor_sync(0xffffffffu, mt0, 1));
        mt0 = fmaxf(mt0, __shfl_xor_sync(0xffffffffu, mt0, 2));
        mt1 = fmaxf(mt1, __shfl_xor_sync(0xffffffffu, mt1, 1));
        mt1 = fmaxf(mt1, __shfl_xor_sync(0xffffffffu, mt1, 2));

        float mn0 = fmaxf(mrow[0], mt0), mn1 = fmaxf(mrow[1], mt1);
        float al0 = exp2fast(mrow[0] - mn0), al1 = exp2fast(mrow[1] - mn1);
        mrow[0] = mn0; mrow[1] = mn1;

        float ls0 = 0.f, ls1 = 0.f;
#pragma unroll
        for (int fn = 0; fn < 8; fn++) {
            sAcc[fn][0] = exp2fast(sAcc[fn][0] - mn0);
            sAcc[fn][1] = exp2fast(sAcc[fn][1] - mn0);
            sAcc[fn][2] = exp2fast(sAcc[fn][2] - mn1);
            sAcc[fn][3] = exp2fast(sAcc[fn][3] - mn1);
            ls0 += sAcc[fn][0] + sAcc[fn][1];
            ls1 += sAcc[fn][2] + sAcc[fn][3];
        }
        ls0 += __shfl_xor_sync(0xffffffffu, ls0, 1);
        ls0 += __shfl_xor_sync(0xffffffffu, ls0, 2);
        ls1 += __shfl_xor_sync(0xffffffffu, ls1, 1);
        ls1 += __shfl_xor_sync(0xffffffffu, ls1, 2);
        lrow[0] = lrow[0] * al0 + ls0;
        lrow[1] = lrow[1] * al1 + ls1;
#pragma unroll
        for (int fn = 0; fn < 8; fn++) {
            oAcc[fn][0] *= al0; oAcc[fn][1] *= al0;
            oAcc[fn][2] *= al1; oAcc[fn][3] *= al1;
        }

        uint32_t ph[4][4], pl[4][4];
#pragma unroll
        for (int kk = 0; kk < 4; kk++) {
#pragma unroll
            for (int half = 0; half < 2; half++) {
                const float* src = sAcc[2 * kk + half];
                float x0 = src[0], x1 = src[1], x2 = src[2], x3 = src[3];
                uint32_t hA = packbf2(x0, x1);
                uint32_t hB = packbf2(x2, x3);
                __nv_bfloat162 hA2 = *(__nv_bfloat162*)&hA;
                __nv_bfloat162 hB2 = *(__nv_bfloat162*)&hB;
                uint32_t lA = packbf2(x0 - __bfloat162float(hA2.x),
                                      x1 - __bfloat162float(hA2.y));
                uint32_t lB = packbf2(x2 - __bfloat162float(hB2.x),
                                      x3 - __bfloat162float(hB2.y));
                ph[kk][half * 2 + 0] = hA;
                ph[kk][half * 2 + 1] = hB;
                pl[kk][half * 2 + 0] = lA;
                pl[kk][half * 2 + 1] = lB;
            }
        }

#pragma unroll
        for (int kk = 0; kk < 4; kk++) {
#pragma unroll
            for (int p = 0; p < 4; p++) {
                uint32_t off = (uint32_t)(p * 16 + rpart) * 144u
                             + (uint32_t)(kk * 16 + cpart) * 2u;
                uint32_t h0, h1, h2, h3, l0, l1, l2, l3;
                ldmx4(h0, h1, h2, h3, stV + off);
                ldmx4(l0, l1, l2, l3, stV + FL_BUF + off);
                uint32_t bh0[2] = {h0, h2}, bh1[2] = {h1, h3};
                uint32_t bl0[2] = {l0, l2}, bl1[2] = {l1, l3};
                mma_bf16(oAcc[2 * p],     ph[kk], bh0);
                mma_bf16(oAcc[2 * p],     ph[kk], bl0);
                mma_bf16(oAcc[2 * p],     pl[kk], bh0);
                mma_bf16(oAcc[2 * p + 1], ph[kk], bh1);
                mma_bf16(oAcc[2 * p + 1], ph[kk], bl1);
                mma_bf16(oAcc[2 * p + 1], pl[kk], bh1);
            }
        }
    }

    float inv0 = 1.f / lrow[0];
    float inv1 = 1.f / lrow[1];
    int gi0 = i0 + w * 16 + gr;
#pragma unroll
    for (int fn = 0; fn < 8; fn++) {
        int col = h * DH_ + fn * 8 + gc;
        {
            float o0 = oAcc[fn][0] * inv0, o1 = oAcc[fn][1] * inv0;
            uint32_t hi = packbf2(o0, o1);
            __nv_bfloat162 h2 = *(__nv_bfloat162*)&hi;
            uint32_t lo = packbf2(o0 - __bfloat162float(h2.x), o1 - __bfloat162float(h2.y));
            size_t o = ((size_t)b * N_ + gi0) * INNER_ + col;
            *(uint32_t*)&g_ah[o] = hi;
            *(uint32_t*)&g_al[o] = lo;
        }
        {
            float o0 = oAcc[fn][2] * inv1, o1 = oAcc[fn][3] * inv1;
            uint32_t hi = packbf2(o0, o1);
            __nv_bfloat162 h2 = *(__nv_bfloat162*)&hi;
            uint32_t lo = packbf2(o0 - __bfloat162float(h2.x), o1 - __bfloat162float(h2.y));
            size_t o = ((size_t)b * N_ + gi0 + 8) * INNER_ + col;
            *(uint32_t*)&g_ah[o] = hi;
            *(uint32_t*)&g_al[o] = lo;
        }
    }
}

// ---------------------------------------------------------------------------
// Launch
// ---------------------------------------------------------------------------
extern "C" void kernel_launch(void* const* d_in, const int* in_sizes, int n_in,
                              void* d_out, int out_size)
{
    const float* x    = (const float*)d_in[0];
    const float* rotq = (const float*)d_in[1];
    const float* rotk = (const float*)d_in[2];
    const float* xl   = (const float*)d_in[3];
    const float* Wq   = (const float*)d_in[4];
    const float* Wkv  = (const float*)d_in[5];
    const float* Wout = (const float*)d_in[6];
    const float* nkv  = (const float*)d_in[7];

    float* out1 = (float*)d_out;
    float* out2 = out1 + (size_t)B_ * N_ * INNER_;

    void *pq, *pah, *pal, *pwh, *pwl, *pmax;
    cudaGetSymbolAddress(&pq, g_q);
    cudaGetSymbolAddress(&pah, g_ah);
    cudaGetSymbolAddress(&pal, g_al);
    cudaGetSymbolAddress(&pwh, g_wh);
    cudaGetSymbolAddress(&pwl, g_wl);
    cudaGetSymbolAddress(&pmax, g_maxbits);

    __nv_bfloat16* ah = (__nv_bfloat16*)pah;
    __nv_bfloat16* al = (__nv_bfloat16*)pal;
    __nv_bfloat16* wh = (__nv_bfloat16*)pwh;
    __nv_bfloat16* wl = (__nv_bfloat16*)pwl;

    cudaFuncSetAttribute(gemm_i8, cudaFuncAttributeMaxDynamicSharedMemorySize, I8_SMEM);
    cudaFuncSetAttribute(gemm_mma3, cudaFuncAttributeMaxDynamicSharedMemorySize, GEMM_SMEM);
    cudaFuncSetAttribute(flash2, cudaFuncAttributeMaxDynamicSharedMemorySize, FL_SMEM);

    // 0) reset absmax scalars (deterministic per call)
    cudaMemsetAsync(pmax, 0, 8);

    // 1) absmax + quantize x / weights; Wout bf16 transpose (independent)
    absmax_xw<<<512, 256>>>(x, Wq, Wkv);
    {
        size_t n4 = (size_t)B_ * N_ * DIM_ / 4;
        quantize_x<<<(unsigned)((n4 + 255) / 256), 256>>>(x);
    }
    transpose_quant_w<<<dim3(96, 32), dim3(32, 8)>>>(Wq, Wkv);
    transpose_split<<<dim3(32, 32), dim3(32, 8)>>>(Wout, wh, wl, 1024);

    // 2) int8 fused q+kv projection: q -> g_q fp32; kv -> out2 rows 1..N
    gemm_i8<<<dim3(3072 / 64, 4096 / 128), 128, I8_SMEM>>>((float*)pq, out2);

    // 3) attention operand prep
    convert_q_rot<<<dim3(N_ / 64, H_, B_), 256>>>(rotq);
    assemble_kv2<<<dim3(KVP_ / 64, H_, B_), 256>>>(xl, nkv, rotk, out2);

    // 4) flash attention -> g_ah/g_al
    flash2<<<dim3(32, H_, B_), 128, FL_SMEM>>>();

    // 5) output projection (bf16 3-term, unchanged)
    gemm_mma3<<<dim3(1024 / 128, 4096 / 128), 256, GEMM_SMEM>>>(
        ah, al, wh, wl, out1);
}

// round 15
// speedup vs baseline: 1.4860x; 1.4860x over previous
#include <cuda_runtime.h>
#include <cuda_bf16.h>
#include <math.h>
#include <stdint.h>

// Problem constants
#define B_      2
#define N_      2048
#define DIM_    1024
#define H_      16
#define DH_     64
#define M_      512
#define INNER_  1024
#define KV_     2561      // M + 1 + N
#define NXL_    2049      // 1 + N
#define KVP_    2624      // KV padded to 41*64

// ---------------------------------------------------------------------------
// Device scratch
// ---------------------------------------------------------------------------
__device__ __align__(16) float g_q   [(size_t)B_ * N_ * INNER_];

__device__ __align__(256) __nv_bfloat16 g_xh[(size_t)B_ * N_ * DIM_];
__device__ __align__(256) __nv_bfloat16 g_xl[(size_t)B_ * N_ * DIM_];
__device__ __align__(256) __nv_bfloat16 g_ah[(size_t)B_ * N_ * INNER_];
__device__ __align__(256) __nv_bfloat16 g_al[(size_t)B_ * N_ * INNER_];
__device__ __align__(256) __nv_bfloat16 g_wh[(size_t)4 * 1024 * 1024];
__device__ __align__(256) __nv_bfloat16 g_wl[(size_t)4 * 1024 * 1024];

// attention operands, bf16 hi/lo
__device__ __align__(256) __nv_bfloat16 g_qbh[(size_t)B_ * H_ * N_ * DH_];
__device__ __align__(256) __nv_bfloat16 g_qbl[(size_t)B_ * H_ * N_ * DH_];
__device__ __align__(256) __nv_bfloat16 g_kbh[(size_t)B_ * H_ * KVP_ * DH_];
__device__ __align__(256) __nv_bfloat16 g_kbl[(size_t)B_ * H_ * KVP_ * DH_];
__device__ __align__(256) __nv_bfloat16 g_vth[(size_t)B_ * H_ * DH_ * KVP_];
__device__ __align__(256) __nv_bfloat16 g_vtl[(size_t)B_ * H_ * DH_ * KVP_];

// ---------------------------------------------------------------------------
// PTX helpers — base sm_103-safe subset
// ---------------------------------------------------------------------------
__device__ __forceinline__ uint32_t smem_u32(const void* p) {
    uint32_t a;
    asm("{ .reg .u64 t; cvta.to.shared.u64 t, %1; cvt.u32.u64 %0, t; }" : "=r"(a) : "l"(p));
    return a;
}

#define CP_ASYNC16(smem, gptr) \
    asm volatile("cp.async.cg.shared.global [%0], [%1], 16;" :: "r"(smem), "l"(gptr) : "memory")
#define CP_COMMIT() asm volatile("cp.async.commit_group;" ::: "memory")
#define CP_WAIT0()  asm volatile("cp.async.wait_group 0;" ::: "memory")
#define CP_WAIT1()  asm volatile("cp.async.wait_group 1;" ::: "memory")

__device__ __forceinline__ void ldmx4(uint32_t& r0, uint32_t& r1, uint32_t& r2, uint32_t& r3,
                                      uint32_t addr) {
    asm volatile("ldmatrix.sync.aligned.m8n8.x4.shared.b16 {%0,%1,%2,%3}, [%4];"
                 : "=r"(r0), "=r"(r1), "=r"(r2), "=r"(r3) : "r"(addr));
}

__device__ __forceinline__ void mma_bf16(float* c, const uint32_t* a, const uint32_t* b) {
    asm volatile(
        "mma.sync.aligned.m16n8k16.row.col.f32.bf16.bf16.f32 "
        "{%0,%1,%2,%3}, {%4,%5,%6,%7}, {%8,%9}, {%0,%1,%2,%3};"
        : "+f"(c[0]), "+f"(c[1]), "+f"(c[2]), "+f"(c[3])
        : "r"(a[0]), "r"(a[1]), "r"(a[2]), "r"(a[3]), "r"(b[0]), "r"(b[1]));
}

// exp2 without MUFU (attention domain x <= 0)
__device__ __forceinline__ float exp2fast(float x) {
    x = fmaxf(x, -126.0f);
    float t = x + 12582912.0f;
    int k = __float_as_int(t) - 0x4b400000;
    float f = x - (t - 12582912.0f);
    float p = 1.3333558e-3f;
    p = fmaf(p, f, 9.6181291e-3f);
    p = fmaf(p, f, 5.5504109e-2f);
    p = fmaf(p, f, 2.4022651e-1f);
    p = fmaf(p, f, 6.9314718e-1f);
    p = fmaf(p, f, 1.0f);
    return __int_as_float(__float_as_int(p) + (k << 23));
}

__device__ __forceinline__ uint32_t packbf2(float a, float b) {
    __nv_bfloat162 t = __floats2bfloat162_rn(a, b);
    return *(uint32_t*)&t;
}
__device__ __forceinline__ uint32_t pack_bf2u(__nv_bfloat16 a, __nv_bfloat16 b) {
    return (uint32_t)__bfloat16_as_ushort(a) | ((uint32_t)__bfloat16_as_ushort(b) << 16);
}

// ---------------------------------------------------------------------------
// fp32 -> bf16 hi/lo split
// ---------------------------------------------------------------------------
__global__ void convert_split(const float* __restrict__ in,
                              __nv_bfloat16* __restrict__ hi,
                              __nv_bfloat16* __restrict__ lo, size_t n4)
{
    size_t i = (size_t)blockIdx.x * blockDim.x + threadIdx.x;
    if (i >= n4) return;
    float4 v = ((const float4*)in)[i];
    __nv_bfloat16 h0 = __float2bfloat16(v.x), h1 = __float2bfloat16(v.y);
    __nv_bfloat16 h2 = __float2bfloat16(v.z), h3 = __float2bfloat16(v.w);
    __nv_bfloat16 l0 = __float2bfloat16(v.x - __bfloat162float(h0));
    __nv_bfloat16 l1 = __float2bfloat16(v.y - __bfloat162float(h1));
    __nv_bfloat16 l2 = __float2bfloat16(v.z - __bfloat162float(h2));
    __nv_bfloat16 l3 = __float2bfloat16(v.w - __bfloat162float(h3));
    ((uint2*)hi)[i] = make_uint2(pack_bf2u(h0, h1), pack_bf2u(h2, h3));
    ((uint2*)lo)[i] = make_uint2(pack_bf2u(l0, l1), pack_bf2u(l2, l3));
}

// Merged weight transpose+split: bx<32 -> Wq; 32<=bx<96 -> Wkv; bx>=96 -> Wout
__global__ void transpose_split_all(const float* __restrict__ Wq,
                                    const float* __restrict__ Wkv,
                                    const float* __restrict__ Wout)
{
    __shared__ float s[32][33];
    int bx = blockIdx.x;
    const float* in;
    __nv_bfloat16 *hi, *lo;
    int Ncols, n0;
    if (bx < 32)      { in = Wq;   hi = g_wh;                lo = g_wl;                Ncols = 1024; n0 = bx * 32; }
    else if (bx < 96) { in = Wkv;  hi = g_wh + (1u << 20);   lo = g_wl + (1u << 20);   Ncols = 2048; n0 = (bx - 32) * 32; }
    else              { in = Wout; hi = g_wh + 3u * (1u << 20); lo = g_wl + 3u * (1u << 20); Ncols = 1024; n0 = (bx - 96) * 32; }
    int k0 = blockIdx.y * 32;
    int tx = threadIdx.x, ty = threadIdx.y;  // 32 x 8
#pragma unroll
    for (int r = 0; r < 4; r++)
        s[ty + r * 8][tx] = in[(size_t)(k0 + ty + r * 8) * Ncols + n0 + tx];
    __syncthreads();
#pragma unroll
    for (int r = 0; r < 4; r++) {
        int row = ty + r * 8;
        float v = s[tx][row];
        __nv_bfloat16 h = __float2bfloat16(v);
        __nv_bfloat16 l = __float2bfloat16(v - __bfloat162float(h));
        size_t o = (size_t)(n0 + row) * 1024 + k0 + tx;
        hi[o] = h;
        lo[o] = l;
    }
}

// ---------------------------------------------------------------------------
// GEMM via mma.sync: CTA 128x128, 256 threads (8 warps 2m x 4n), warp 64x32,
// BK=32, 2-stage cp.async, occupancy 2. 3-term bf16 split (proven config).
// mode 0: fused qkv (grid x covers N=3072): col<1024 -> outQ (g_q, pitch 1024),
//         col>=1024 -> out2 scatter ONLY (next_xl rows 1..N)
// mode 1: plain write to outQ, pitch 1024
// ---------------------------------------------------------------------------
#define STAGE_BYTES 40960
#define GEMM_SMEM   (2 * STAGE_BYTES + 128)

__global__ __launch_bounds__(256, 2) void gemm_mma3(
    const __nv_bfloat16* __restrict__ Ah, const __nv_bfloat16* __restrict__ Al,
    const __nv_bfloat16* __restrict__ Bh, const __nv_bfloat16* __restrict__ Bl,
    float* __restrict__ outQ, float* __restrict__ out2, int mode)
{
    extern __shared__ char dsm[];
    const int tid = threadIdx.x;
    const int lane = tid & 31;
    const int wid = tid >> 5;
    const int bm = blockIdx.y * 128, bn = blockIdx.x * 128;
    const int warpM = (wid >> 2) * 64;
    const int warpN = (wid & 3) * 32;

    uint32_t sb = (smem_u32(dsm) + 127) & ~127u;

    auto load_stage = [&](int chunk, int stage) {
        const int k0 = chunk * 32;
        uint32_t base = sb + stage * STAGE_BYTES;
#pragma unroll
        for (int e = 0; e < 8; e++) {
            int lin = e * 256 + tid;
            int buf = lin >> 9;
            int idx = lin & 511;
            int r = idx >> 2;
            int c = idx & 3;
            uint32_t soff = (uint32_t)buf * 10240u + (uint32_t)r * 80u + (uint32_t)c * 16u;
            const __nv_bfloat16* gp;
            if (buf == 0)      gp = Ah + (size_t)(bm + r) * 1024 + k0;
            else if (buf == 1) gp = Al + (size_t)(bm + r) * 1024 + k0;
            else if (buf == 2) gp = Bh + (size_t)(bn + r) * 1024 + k0;
            else               gp = Bl + (size_t)(bn + r) * 1024 + k0;
            CP_ASYNC16(base + soff, gp + c * 8);
        }
        CP_COMMIT();
    };

    float acc[4][4][4];
#pragma unroll
    for (int i = 0; i < 4; i++)
#pragma unroll
        for (int j = 0; j < 4; j++)
#pragma unroll
            for (int k = 0; k < 4; k++) acc[i][j][k] = 0.f;

    load_stage(0, 0);

    const int NC = 32;
    for (int ch = 0; ch < NC; ch++) {
        int s = ch & 1;
        if (ch + 1 < NC) { load_stage(ch + 1, s ^ 1); CP_WAIT1(); }
        else             { CP_WAIT0(); }
        __syncthreads();

        uint32_t st = sb + s * STAGE_BYTES;
        uint32_t aH = st, aL = st + 10240, bH = st + 20480, bL = st + 30720;

#pragma unroll
        for (int kk = 0; kk < 2; kk++) {
            uint32_t bh[4][2], bl[4][2];
#pragma unroll
            for (int p = 0; p < 2; p++) {
                uint32_t off = (uint32_t)(warpN + p * 16 + (lane & 15)) * 80u
                             + (uint32_t)kk * 32u + (uint32_t)(lane >> 4) * 16u;
                uint32_t r0, r1, r2, r3;
                ldmx4(r0, r1, r2, r3, bH + off);
                bh[p * 2][0] = r0; bh[p * 2 + 1][0] = r1;
                bh[p * 2][1] = r2; bh[p * 2 + 1][1] = r3;
                ldmx4(r0, r1, r2, r3, bL + off);
                bl[p * 2][0] = r0; bl[p * 2 + 1][0] = r1;
                bl[p * 2][1] = r2; bl[p * 2 + 1][1] = r3;
            }
#pragma unroll
            for (int fm = 0; fm < 4; fm++) {
                uint32_t off = (uint32_t)(warpM + fm * 16 + (lane & 15)) * 80u
                             + (uint32_t)kk * 32u + (uint32_t)(lane >> 4) * 16u;
                uint32_t ah[4], al[4];
                ldmx4(ah[0], ah[1], ah[2], ah[3], aH + off);
                ldmx4(al[0], al[1], al[2], al[3], aL + off);
#pragma unroll
                for (int fn = 0; fn < 4; fn++) {
                    mma_bf16(acc[fm][fn], ah, bh[fn]);
                    mma_bf16(acc[fm][fn], ah, bl[fn]);
                    mma_bf16(acc[fm][fn], al, bh[fn]);
                }
            }
        }
        __syncthreads();
    }

    const int gr = lane >> 2;
    const int gc = (lane & 3) * 2;
#pragma unroll
    for (int fm = 0; fm < 4; fm++) {
#pragma unroll
        for (int fn = 0; fn < 4; fn++) {
            int row0 = bm + warpM + fm * 16 + gr;
            int col  = bn + warpN + fn * 8 + gc;
#pragma unroll
            for (int half = 0; half < 2; half++) {
                int rr = row0 + half * 8;
                float v0 = acc[fm][fn][2 * half], v1 = acc[fm][fn][2 * half + 1];
                if (mode == 1 || col < 1024) {
                    *(float2*)&outQ[(size_t)rr * 1024 + col] = make_float2(v0, v1);
                } else {
                    int ckv = col - 1024;
                    int s = ckv >> 10;
                    int hh = (ckv & 1023) >> 6;
                    int d = ckv & 63;
                    int b = rr >> 11;
                    int n = rr & 2047;
                    size_t o = ((((size_t)s * B_ + b) * H_ + hh) * NXL_ + n + 1) * 64 + d;
                    *(float2*)&out2[o] = make_float2(v0, v1);
                }
            }
        }
    }
}

// ---------------------------------------------------------------------------
// Q conversion: rotary + scale*log2(e), bf16 hi/lo, layout (b,h,i,d)
// (MUFU __sincosf: max err ~2e-7, far below bf16 split noise)
// ---------------------------------------------------------------------------
__global__ void convert_q_rot(const float* __restrict__ rotq)
{
    const int i0 = blockIdx.x * 64;
    const int h = blockIdx.y, b = blockIdx.z;
    const int tid = threadIdx.x;
    const size_t bh = (size_t)b * H_ + h;
    const float F = 0.18033688011112042f;   // 0.125 * log2(e)
#pragma unroll
    for (int e = 0; e < 16; e++) {
        int idx = e * 256 + tid;
        int i = i0 + (idx >> 6);
        int d = idx & 63;
        int d2 = d ^ 32;
        const float* qrow = &g_q[((size_t)b * N_ + i) * INNER_ + h * DH_];
        float q0 = qrow[d], q1 = qrow[d2];
        float pos = rotq[(size_t)i * DH_ + d];
        float sn, cs;
        __sincosf(pos, &sn, &cs);
        float qr = (q0 * cs + ((d < 32) ? -q1 : q1) * sn) * F;
        __nv_bfloat16 qh = __float2bfloat16(qr);
        __nv_bfloat16 ql = __float2bfloat16(qr - __bfloat162float(qh));
        size_t o = (bh * N_ + i) * DH_ + d;
        g_qbh[o] = qh;
        g_qbl[o] = ql;
    }
}

// ---------------------------------------------------------------------------
// Assemble K (rotated, (b,h,j,d)) and Vt ((b,h,d,j)); also out2 null row.
// Reads fresh k/v projections from out2 (written by fused GEMM epilogue).
// ---------------------------------------------------------------------------
__global__ void assemble_kv2(const float* __restrict__ xl,
                             const float* __restrict__ nullkv,
                             const float* __restrict__ rotk,
                             float* __restrict__ out2)
{
    __shared__ uint16_t svh[64][72], svl[64][72];
    const int j0 = blockIdx.x * 64;
    const int h = blockIdx.y, b = blockIdx.z;
    const int tid = threadIdx.x;
    const size_t bh = (size_t)b * H_ + h;

#pragma unroll
    for (int e = 0; e < 16; e++) {
        int idx = e * 256 + tid;
        int jl = idx >> 6;
        int j = j0 + jl;
        int d = idx & 63;
        int d2 = d ^ 32;

        float k0 = 0.f, k1 = 0.f, v0 = 0.f, pos = 0.f;
        if (j < M_) {
            size_t base = (((size_t)b * H_ + h) * M_ + j) * DH_;
            size_t voff = (size_t)B_ * H_ * M_ * DH_;
            k0 = xl[base + d];
            k1 = xl[base + d2];
            v0 = xl[voff + base + d];
            pos = rotk[(size_t)j * DH_ + d];
        } else if (j == M_) {
            k0 = nullkv[h * DH_ + d];
            k1 = nullkv[h * DH_ + d2];
            v0 = nullkv[H_ * DH_ + h * DH_ + d];
            pos = rotk[(size_t)j * DH_ + d];
            out2[(((size_t)0 * B_ + b) * H_ + h) * NXL_ * 64 + d] = k0;
            out2[(((size_t)1 * B_ + b) * H_ + h) * NXL_ * 64 + d] = v0;
        } else if (j < KV_) {
            int n = j - M_ - 1;
            size_t kbase = ((((size_t)0 * B_ + b) * H_ + h) * NXL_ + n + 1) * 64;
            size_t vbase = ((((size_t)1 * B_ + b) * H_ + h) * NXL_ + n + 1) * 64;
            k0 = out2[kbase + d];
            k1 = out2[kbase + d2];
            v0 = out2[vbase + d];
            pos = rotk[(size_t)j * DH_ + d];
        }
        float sn, cs;
        __sincosf(pos, &sn, &cs);
        float rot = (d < 32) ? -k1 : k1;
        float kr = k0 * cs + rot * sn;

        __nv_bfloat16 kh = __float2bfloat16(kr);
        __nv_bfloat16 kl = __float2bfloat16(kr - __bfloat162float(kh));
        size_t ko = (bh * KVP_ + j) * DH_ + d;
        g_kbh[ko] = kh;
        g_kbl[ko] = kl;

        __nv_bfloat16 vh = __float2bfloat16(v0);
        __nv_bfloat16 vl = __float2bfloat16(v0 - __bfloat162float(vh));
        svh[d][jl] = __bfloat16_as_ushort(vh);
        svl[d][jl] = __bfloat16_as_ushort(vl);
    }
    __syncthreads();

#pragma unroll
    for (int e = 0; e < 8; e++) {
        int idx = e * 256 + tid;
        int d = idx >> 5;
        int jj = (idx & 31) * 2;
        uint32_t ph = (uint32_t)svh[d][jj] | ((uint32_t)svh[d][jj + 1] << 16);
        uint32_t pl = (uint32_t)svl[d][jj] | ((uint32_t)svl[d][jj + 1] << 16);
        size_t o = (bh * DH_ + d) * KVP_ + j0 + jj;
        *(uint32_t*)&g_vth[o] = ph;
        *(uint32_t*)&g_vtl[o] = pl;
    }
}

// ---------------------------------------------------------------------------
// Flash attention: mma.sync 3-term S, 3-term PV, fp32 l (proven numerics)
// ---------------------------------------------------------------------------
#define FL_BUF   9216
#define FL_SMEM  (10 * FL_BUF)

__global__ __launch_bounds__(128, 2) void flash2()
{
    extern __shared__ __align__(16) char fsm[];
    const int tid = threadIdx.x;
    const int lane = tid & 31;
    const int w = tid >> 5;
    const int bx = 31 - (int)blockIdx.x;
    const int h = blockIdx.y, b = blockIdx.z;
    const int i0 = bx * 64;
    const size_t bh = (size_t)b * H_ + h;

    uint32_t sb = smem_u32(fsm);

    {
        const __nv_bfloat16* q0 = g_qbh + (bh * N_ + i0) * DH_;
        const __nv_bfloat16* q1 = g_qbl + (bh * N_ + i0) * DH_;
#pragma unroll
        for (int e = 0; e < 8; e++) {
            int lin = e * 128 + tid;
            int buf = lin >> 9;
            int idx = lin & 511;
            int r = idx >> 3, c = idx & 7;
            const __nv_bfloat16* gp = (buf == 0 ? q0 : q1) + r * 64 + c * 8;
            CP_ASYNC16(sb + buf * FL_BUF + r * 144 + c * 16, gp);
        }
    }

    const __nv_bfloat16* kh0 = g_kbh + bh * KVP_ * DH_;
    const __nv_bfloat16* kl0 = g_kbl + bh * KVP_ * DH_;
    const __nv_bfloat16* vh0 = g_vth + bh * DH_ * KVP_;
    const __nv_bfloat16* vl0 = g_vtl + bh * DH_ * KVP_;

    auto load_kv = [&](int t, int s) {
        int j0 = t * 64;
        uint32_t base = sb + 2 * FL_BUF + s * (4 * FL_BUF);
#pragma unroll
        for (int e = 0; e < 16; e++) {
            int lin = e * 128 + tid;
            int buf = lin >> 9;
            int idx = lin & 511;
            int r = idx >> 3, c = idx & 7;
            const __nv_bfloat16* gp;
            if (buf == 0)      gp = kh0 + (size_t)(j0 + r) * 64 + c * 8;
            else if (buf == 1) gp = kl0 + (size_t)(j0 + r) * 64 + c * 8;
            else if (buf == 2) gp = vh0 + (size_t)r * KVP_ + j0 + c * 8;
            else               gp = vl0 + (size_t)r * KVP_ + j0 + c * 8;
            CP_ASYNC16(base + buf * FL_BUF + r * 144 + c * 16, gp);
        }
    };

    load_kv(0, 0);
    CP_COMMIT();

    const int rpart = ((lane >> 3) & 1) * 8 + (lane & 7);
    const int cpart = (lane >> 4) * 8;
    const int gr = lane >> 2;
    const int gc = (lane & 3) * 2;

    uint32_t qh[4][4], ql[4][4];
    float oAcc[8][4];
    float mrow[2] = {-1e30f, -1e30f};
    float lrow[2] = {0.f, 0.f};
#pragma unroll
    for (int fn = 0; fn < 8; fn++)
#pragma unroll
        for (int e = 0; e < 4; e++) oAcc[fn][e] = 0.f;

    const int ntiles = bx + 10;
    for (int t = 0; t < ntiles; t++) {
        if (t > 0) __syncthreads();
        if (t + 1 < ntiles) { load_kv(t + 1, (t + 1) & 1); CP_COMMIT(); CP_WAIT1(); }
        else                { CP_WAIT0(); }
        __syncthreads();

        if (t == 0) {
#pragma unroll
            for (int kk = 0; kk < 4; kk++) {
                uint32_t off = (uint32_t)(w * 16 + (lane & 15)) * 144u
                             + (uint32_t)(kk * 16 + cpart) * 2u;
                ldmx4(qh[kk][0], qh[kk][1], qh[kk][2], qh[kk][3], sb + off);
                ldmx4(ql[kk][0], ql[kk][1], ql[kk][2], ql[kk][3], sb + FL_BUF + off);
            }
        }

        uint32_t stK = sb + 2 * FL_BUF + (t & 1) * (4 * FL_BUF);
        uint32_t stV = stK + 2 * FL_BUF;

        float sAcc[8][4];
#pragma unroll
        for (int fn = 0; fn < 8; fn++)
#pragma unroll
            for (int e = 0; e < 4; e++) sAcc[fn][e] = 0.f;

#pragma unroll
        for (int kk = 0; kk < 4; kk++) {
#pragma unroll
            for (int p = 0; p < 4; p++) {
                uint32_t off = (uint32_t)(p * 16 + rpart) * 144u
                             + (uint32_t)(kk * 16 + cpart) * 2u;
                uint32_t h0, h1, h2, h3, l0, l1, l2, l3;
                ldmx4(h0, h1, h2, h3, stK + off);
                ldmx4(l0, l1, l2, l3, stK + FL_BUF + off);
                uint32_t bh0[2] = {h0, h2}, bh1[2] = {h1, h3};
                uint32_t bl0[2] = {l0, l2}, bl1[2] = {l1, l3};
                mma_bf16(sAcc[2 * p],     qh[kk], bh0);
                mma_bf16(sAcc[2 * p],     qh[kk], bl0);
                mma_bf16(sAcc[2 * p],     ql[kk], bh0);
                mma_bf16(sAcc[2 * p + 1], qh[kk], bh1);
                mma_bf16(sAcc[2 * p + 1], qh[kk], bl1);
                mma_bf16(sAcc[2 * p + 1], ql[kk], bh1);
            }
        }

        if (t >= ntiles - 2) {
            int j0 = t * 64;
#pragma unroll
            for (int fn = 0; fn < 8; fn++) {
#pragma unroll
                for (int e = 0; e < 4; e++) {
                    int gj = j0 + fn * 8 + gc + (e & 1);
                    int gi = i0 + w * 16 + gr + (e >> 1) * 8;
                    if (gj > gi + (KV_ - N_)) sAcc[fn][e] = -1e30f;
                }
            }
        }

        float mt0 = -1e30f, mt1 = -1e30f;
#pragma unroll
        for (int fn = 0; fn < 8; fn++) {
            mt0 = fmaxf(mt0, fmaxf(sAcc[fn][0], sAcc[fn][1]));
            mt1 = fmaxf(mt1, fmaxf(sAcc[fn][2], sAcc[fn][3]));
        }
        mt0 = fmaxf(mt0, __shfl_xor_sync(0xffffffffu, mt0, 1));
        mt0 = fmaxf(mt0, __shfl_xor_sync(0xffffffffu, mt0, 2));
        mt1 = fmaxf(mt1, __shfl_xor_sync(0xffffffffu, mt1, 1));
        mt1 = fmaxf(mt1, __shfl_xor_sync(0xffffffffu, mt1, 2));

        float mn0 = fmaxf(mrow[0], mt0), mn1 = fmaxf(mrow[1], mt1);
        float al0 = exp2fast(mrow[0] - mn0), al1 = exp2fast(mrow[1] - mn1);
        mrow[0] = mn0; mrow[1] = mn1;

        float ls0 = 0.f, ls1 = 0.f;
#pragma unroll
        for (int fn = 0; fn < 8; fn++) {
            sAcc[fn][0] = exp2fast(sAcc[fn][0] - mn0);
            sAcc[fn][1] = exp2fast(sAcc[fn][1] - mn0);
            sAcc[fn][2] = exp2fast(sAcc[fn][2] - mn1);
            sAcc[fn][3] = exp2fast(sAcc[fn][3] - mn1);
            ls0 += sAcc[fn][0] + sAcc[fn][1];
            ls1 += sAcc[fn][2] + sAcc[fn][3];
        }
        ls0 += __shfl_xor_sync(0xffffffffu, ls0, 1);
        ls0 += __shfl_xor_sync(0xffffffffu, ls0, 2);
        ls1 += __shfl_xor_sync(0xffffffffu, ls1, 1);
        ls1 += __shfl_xor_sync(0xffffffffu, ls1, 2);
        lrow[0] = lrow[0] * al0 + ls0;
        lrow[1] = lrow[1] * al1 + ls1;
#pragma unroll
        for (int fn = 0; fn < 8; fn++) {
            oAcc[fn][0] *= al0; oAcc[fn][1] *= al0;
            oAcc[fn][2] *= al1; oAcc[fn][3] *= al1;
        }

        uint32_t ph[4][4], pl[4][4];
#pragma unroll
        for (int kk = 0; kk < 4; kk++) {
#pragma unroll
            for (int half = 0; half < 2; half++) {
                const float* src = sAcc[2 * kk + half];
                float x0 = src[0], x1 = src[1], x2 = src[2], x3 = src[3];
                uint32_t hA = packbf2(x0, x1);
                uint32_t hB = packbf2(x2, x3);
                __nv_bfloat162 hA2 = *(__nv_bfloat162*)&hA;
                __nv_bfloat162 hB2 = *(__nv_bfloat162*)&hB;
                uint32_t lA = packbf2(x0 - __bfloat162float(hA2.x),
                                      x1 - __bfloat162float(hA2.y));
                uint32_t lB = packbf2(x2 - __bfloat162float(hB2.x),
                                      x3 - __bfloat162float(hB2.y));
                ph[kk][half * 2 + 0] = hA;
                ph[kk][half * 2 + 1] = hB;
                pl[kk][half * 2 + 0] = lA;
                pl[kk][half * 2 + 1] = lB;
            }
        }

#pragma unroll
        for (int kk = 0; kk < 4; kk++) {
#pragma unroll
            for (int p = 0; p < 4; p++) {
                uint32_t off = (uint32_t)(p * 16 + rpart) * 144u
                             + (uint32_t)(kk * 16 + cpart) * 2u;
                uint32_t h0, h1, h2, h3, l0, l1, l2, l3;
                ldmx4(h0, h1, h2, h3, stV + off);
                ldmx4(l0, l1, l2, l3, stV + FL_BUF + off);
                uint32_t bh0[2] = {h0, h2}, bh1[2] = {h1, h3};
                uint32_t bl0[2] = {l0, l2}, bl1[2] = {l1, l3};
                mma_bf16(oAcc[2 * p],     ph[kk], bh0);
                mma_bf16(oAcc[2 * p],     ph[kk], bl0);
                mma_bf16(oAcc[2 * p],     pl[kk], bh0);
                mma_bf16(oAcc[2 * p + 1], ph[kk], bh1);
                mma_bf16(oAcc[2 * p + 1], ph[kk], bl1);
                mma_bf16(oAcc[2 * p + 1], pl[kk], bh1);
            }
        }
    }

    float inv0 = 1.f / lrow[0];
    float inv1 = 1.f / lrow[1];
    int gi0 = i0 + w * 16 + gr;
#pragma unroll
    for (int fn = 0; fn < 8; fn++) {
        int col = h * DH_ + fn * 8 + gc;
        {
            float o0 = oAcc[fn][0] * inv0, o1 = oAcc[fn][1] * inv0;
            uint32_t hi = packbf2(o0, o1);
            __nv_bfloat162 h2 = *(__nv_bfloat162*)&hi;
            uint32_t lo = packbf2(o0 - __bfloat162float(h2.x), o1 - __bfloat162float(h2.y));
            size_t o = ((size_t)b * N_ + gi0) * INNER_ + col;
            *(uint32_t*)&g_ah[o] = hi;
            *(uint32_t*)&g_al[o] = lo;
        }
        {
            float o0 = oAcc[fn][2] * inv1, o1 = oAcc[fn][3] * inv1;
            uint32_t hi = packbf2(o0, o1);
            __nv_bfloat162 h2 = *(__nv_bfloat162*)&hi;
            uint32_t lo = packbf2(o0 - __bfloat162float(h2.x), o1 - __bfloat162float(h2.y));
            size_t o = ((size_t)b * N_ + gi0 + 8) * INNER_ + col;
            *(uint32_t*)&g_ah[o] = hi;
            *(uint32_t*)&g_al[o] = lo;
        }
    }
}

// ---------------------------------------------------------------------------
// Launch
// ---------------------------------------------------------------------------
extern "C" void kernel_launch(void* const* d_in, const int* in_sizes, int n_in,
                              void* d_out, int out_size)
{
    const float* x    = (const float*)d_in[0];
    const float* rotq = (const float*)d_in[1];
    const float* rotk = (const float*)d_in[2];
    const float* xl   = (const float*)d_in[3];
    const float* Wq   = (const float*)d_in[4];
    const float* Wkv  = (const float*)d_in[5];
    const float* Wout = (const float*)d_in[6];
    const float* nkv  = (const float*)d_in[7];

    float* out1 = (float*)d_out;
    float* out2 = out1 + (size_t)B_ * N_ * INNER_;

    void *pq, *pxh, *pxl, *pah, *pal, *pwh, *pwl;
    cudaGetSymbolAddress(&pq, g_q);
    cudaGetSymbolAddress(&pxh, g_xh);
    cudaGetSymbolAddress(&pxl, g_xl);
    cudaGetSymbolAddress(&pah, g_ah);
    cudaGetSymbolAddress(&pal, g_al);
    cudaGetSymbolAddress(&pwh, g_wh);
    cudaGetSymbolAddress(&pwl, g_wl);

    __nv_bfloat16* xh = (__nv_bfloat16*)pxh;
    __nv_bfloat16* xlo = (__nv_bfloat16*)pxl;
    __nv_bfloat16* ah = (__nv_bfloat16*)pah;
    __nv_bfloat16* al = (__nv_bfloat16*)pal;
    __nv_bfloat16* wh = (__nv_bfloat16*)pwh;
    __nv_bfloat16* wl = (__nv_bfloat16*)pwl;

    cudaFuncSetAttribute(gemm_mma3, cudaFuncAttributeMaxDynamicSharedMemorySize, GEMM_SMEM);
    cudaFuncSetAttribute(flash2, cudaFuncAttributeMaxDynamicSharedMemorySize, FL_SMEM);

    // 1) conversions + weight prep (single merged transpose launch)
    {
        size_t n4 = (size_t)B_ * N_ * DIM_ / 4;
        convert_split<<<(unsigned)((n4 + 255) / 256), 256>>>(x, xh, xlo, n4);
    }
    transpose_split_all<<<dim3(128, 32), dim3(32, 8)>>>(Wq, Wkv, Wout);

    // 2) fused q+kv projection (N=3072): q -> g_q; kv -> out2 rows 1..N
    gemm_mma3<<<dim3(3072 / 128, 4096 / 128), 256, GEMM_SMEM>>>(
        xh, xlo, wh, wl, (float*)pq, out2, 0);

    // 3) attention operand prep (assemble reads kv from out2; writes null row)
    convert_q_rot<<<dim3(N_ / 64, H_, B_), 256>>>(rotq);
    assemble_kv2<<<dim3(KVP_ / 64, H_, B_), 256>>>(xl, nkv, rotk, out2);

    // 4) flash attention -> g_ah/g_al
    flash2<<<dim3(32, H_, B_), 128, FL_SMEM>>>();

    // 5) output projection
    gemm_mma3<<<dim3(1024 / 128, 4096 / 128), 256, GEMM_SMEM>>>(
        ah, al, wh + 3u * (1u << 20), wl + 3u * (1u << 20), out1, nullptr, 1);
}

// round 16
// speedup vs baseline: 1.4904x; 1.0029x over previous
#include <cuda_runtime.h>
#include <cuda_bf16.h>
#include <math.h>
#include <stdint.h>

// Problem constants
#define B_      2
#define N_      2048
#define DIM_    1024
#define H_      16
#define DH_     64
#define M_      512
#define INNER_  1024
#define KV_     2561      // M + 1 + N
#define NXL_    2049      // 1 + N
#define KVP_    2624      // KV padded to 41*64

// ---------------------------------------------------------------------------
// Device scratch
// ---------------------------------------------------------------------------
__device__ __align__(16) float g_q   [(size_t)B_ * N_ * INNER_];

__device__ __align__(256) __nv_bfloat16 g_xh[(size_t)B_ * N_ * DIM_];
__device__ __align__(256) __nv_bfloat16 g_xl[(size_t)B_ * N_ * DIM_];
__device__ __align__(256) __nv_bfloat16 g_ah[(size_t)B_ * N_ * INNER_];
__device__ __align__(256) __nv_bfloat16 g_al[(size_t)B_ * N_ * INNER_];
__device__ __align__(256) __nv_bfloat16 g_wh[(size_t)4 * 1024 * 1024];
__device__ __align__(256) __nv_bfloat16 g_wl[(size_t)4 * 1024 * 1024];

// attention K/V operands, bf16 hi/lo
__device__ __align__(256) __nv_bfloat16 g_kbh[(size_t)B_ * H_ * KVP_ * DH_];
__device__ __align__(256) __nv_bfloat16 g_kbl[(size_t)B_ * H_ * KVP_ * DH_];
__device__ __align__(256) __nv_bfloat16 g_vth[(size_t)B_ * H_ * DH_ * KVP_];
__device__ __align__(256) __nv_bfloat16 g_vtl[(size_t)B_ * H_ * DH_ * KVP_];

// ---------------------------------------------------------------------------
// PTX helpers — base sm_103-safe subset
// ---------------------------------------------------------------------------
__device__ __forceinline__ uint32_t smem_u32(const void* p) {
    uint32_t a;
    asm("{ .reg .u64 t; cvta.to.shared.u64 t, %1; cvt.u32.u64 %0, t; }" : "=r"(a) : "l"(p));
    return a;
}

#define CP_ASYNC16(smem, gptr) \
    asm volatile("cp.async.cg.shared.global [%0], [%1], 16;" :: "r"(smem), "l"(gptr) : "memory")
#define CP_COMMIT() asm volatile("cp.async.commit_group;" ::: "memory")
#define CP_WAIT0()  asm volatile("cp.async.wait_group 0;" ::: "memory")
#define CP_WAIT1()  asm volatile("cp.async.wait_group 1;" ::: "memory")

__device__ __forceinline__ void ldmx4(uint32_t& r0, uint32_t& r1, uint32_t& r2, uint32_t& r3,
                                      uint32_t addr) {
    asm volatile("ldmatrix.sync.aligned.m8n8.x4.shared.b16 {%0,%1,%2,%3}, [%4];"
                 : "=r"(r0), "=r"(r1), "=r"(r2), "=r"(r3) : "r"(addr));
}

__device__ __forceinline__ void mma_bf16(float* c, const uint32_t* a, const uint32_t* b) {
    asm volatile(
        "mma.sync.aligned.m16n8k16.row.col.f32.bf16.bf16.f32 "
        "{%0,%1,%2,%3}, {%4,%5,%6,%7}, {%8,%9}, {%0,%1,%2,%3};"
        : "+f"(c[0]), "+f"(c[1]), "+f"(c[2]), "+f"(c[3])
        : "r"(a[0]), "r"(a[1]), "r"(a[2]), "r"(a[3]), "r"(b[0]), "r"(b[1]));
}

// exp2 without MUFU (attention domain x <= 0)
__device__ __forceinline__ float exp2fast(float x) {
    x = fmaxf(x, -126.0f);
    float t = x + 12582912.0f;
    int k = __float_as_int(t) - 0x4b400000;
    float f = x - (t - 12582912.0f);
    float p = 1.3333558e-3f;
    p = fmaf(p, f, 9.6181291e-3f);
    p = fmaf(p, f, 5.5504109e-2f);
    p = fmaf(p, f, 2.4022651e-1f);
    p = fmaf(p, f, 6.9314718e-1f);
    p = fmaf(p, f, 1.0f);
    return __int_as_float(__float_as_int(p) + (k << 23));
}

__device__ __forceinline__ uint32_t packbf2(float a, float b) {
    __nv_bfloat162 t = __floats2bfloat162_rn(a, b);
    return *(uint32_t*)&t;
}
__device__ __forceinline__ uint32_t pack_bf2u(__nv_bfloat16 a, __nv_bfloat16 b) {
    return (uint32_t)__bfloat16_as_ushort(a) | ((uint32_t)__bfloat16_as_ushort(b) << 16);
}

// ---------------------------------------------------------------------------
// fp32 -> bf16 hi/lo split
// ---------------------------------------------------------------------------
__global__ void convert_split(const float* __restrict__ in,
                              __nv_bfloat16* __restrict__ hi,
                              __nv_bfloat16* __restrict__ lo, size_t n4)
{
    size_t i = (size_t)blockIdx.x * blockDim.x + threadIdx.x;
    if (i >= n4) return;
    float4 v = ((const float4*)in)[i];
    __nv_bfloat16 h0 = __float2bfloat16(v.x), h1 = __float2bfloat16(v.y);
    __nv_bfloat16 h2 = __float2bfloat16(v.z), h3 = __float2bfloat16(v.w);
    __nv_bfloat16 l0 = __float2bfloat16(v.x - __bfloat162float(h0));
    __nv_bfloat16 l1 = __float2bfloat16(v.y - __bfloat162float(h1));
    __nv_bfloat16 l2 = __float2bfloat16(v.z - __bfloat162float(h2));
    __nv_bfloat16 l3 = __float2bfloat16(v.w - __bfloat162float(h3));
    ((uint2*)hi)[i] = make_uint2(pack_bf2u(h0, h1), pack_bf2u(h2, h3));
    ((uint2*)lo)[i] = make_uint2(pack_bf2u(l0, l1), pack_bf2u(l2, l3));
}

// Merged weight transpose+split: bx<32 -> Wq; 32<=bx<96 -> Wkv; bx>=96 -> Wout
__global__ void transpose_split_all(const float* __restrict__ Wq,
                                    const float* __restrict__ Wkv,
                                    const float* __restrict__ Wout)
{
    __shared__ float s[32][33];
    int bx = blockIdx.x;
    const float* in;
    __nv_bfloat16 *hi, *lo;
    int Ncols, n0;
    if (bx < 32)      { in = Wq;   hi = g_wh;                lo = g_wl;                Ncols = 1024; n0 = bx * 32; }
    else if (bx < 96) { in = Wkv;  hi = g_wh + (1u << 20);   lo = g_wl + (1u << 20);   Ncols = 2048; n0 = (bx - 32) * 32; }
    else              { in = Wout; hi = g_wh + 3u * (1u << 20); lo = g_wl + 3u * (1u << 20); Ncols = 1024; n0 = (bx - 96) * 32; }
    int k0 = blockIdx.y * 32;
    int tx = threadIdx.x, ty = threadIdx.y;  // 32 x 8
#pragma unroll
    for (int r = 0; r < 4; r++)
        s[ty + r * 8][tx] = in[(size_t)(k0 + ty + r * 8) * Ncols + n0 + tx];
    __syncthreads();
#pragma unroll
    for (int r = 0; r < 4; r++) {
        int row = ty + r * 8;
        float v = s[tx][row];
        __nv_bfloat16 h = __float2bfloat16(v);
        __nv_bfloat16 l = __float2bfloat16(v - __bfloat162float(h));
        size_t o = (size_t)(n0 + row) * 1024 + k0 + tx;
        hi[o] = h;
        lo[o] = l;
    }
}

// ---------------------------------------------------------------------------
// GEMM via mma.sync: CTA 128x128, 256 threads (8 warps 2m x 4n), warp 64x32,
// BK=32, 2-stage cp.async, occupancy 2. 3-term bf16 split (proven config).
// mode 0: fused qkv (grid x covers N=3072): col<1024 -> outQ (g_q, pitch 1024),
//         col>=1024 -> out2 scatter ONLY (next_xl rows 1..N)
// mode 1: plain write to outQ, pitch 1024
// ---------------------------------------------------------------------------
#define STAGE_BYTES 40960
#define GEMM_SMEM   (2 * STAGE_BYTES + 128)

__global__ __launch_bounds__(256, 2) void gemm_mma3(
    const __nv_bfloat16* __restrict__ Ah, const __nv_bfloat16* __restrict__ Al,
    const __nv_bfloat16* __restrict__ Bh, const __nv_bfloat16* __restrict__ Bl,
    float* __restrict__ outQ, float* __restrict__ out2, int mode)
{
    extern __shared__ char dsm[];
    const int tid = threadIdx.x;
    const int lane = tid & 31;
    const int wid = tid >> 5;
    const int bm = blockIdx.y * 128, bn = blockIdx.x * 128;
    const int warpM = (wid >> 2) * 64;
    const int warpN = (wid & 3) * 32;

    uint32_t sb = (smem_u32(dsm) + 127) & ~127u;

    auto load_stage = [&](int chunk, int stage) {
        const int k0 = chunk * 32;
        uint32_t base = sb + stage * STAGE_BYTES;
#pragma unroll
        for (int e = 0; e < 8; e++) {
            int lin = e * 256 + tid;
            int buf = lin >> 9;
            int idx = lin & 511;
            int r = idx >> 2;
            int c = idx & 3;
            uint32_t soff = (uint32_t)buf * 10240u + (uint32_t)r * 80u + (uint32_t)c * 16u;
            const __nv_bfloat16* gp;
            if (buf == 0)      gp = Ah + (size_t)(bm + r) * 1024 + k0;
            else if (buf == 1) gp = Al + (size_t)(bm + r) * 1024 + k0;
            else if (buf == 2) gp = Bh + (size_t)(bn + r) * 1024 + k0;
            else               gp = Bl + (size_t)(bn + r) * 1024 + k0;
            CP_ASYNC16(base + soff, gp + c * 8);
        }
        CP_COMMIT();
    };

    float acc[4][4][4];
#pragma unroll
    for (int i = 0; i < 4; i++)
#pragma unroll
        for (int j = 0; j < 4; j++)
#pragma unroll
            for (int k = 0; k < 4; k++) acc[i][j][k] = 0.f;

    load_stage(0, 0);

    const int NC = 32;
    for (int ch = 0; ch < NC; ch++) {
        int s = ch & 1;
        if (ch + 1 < NC) { load_stage(ch + 1, s ^ 1); CP_WAIT1(); }
        else             { CP_WAIT0(); }
        __syncthreads();

        uint32_t st = sb + s * STAGE_BYTES;
        uint32_t aH = st, aL = st + 10240, bH = st + 20480, bL = st + 30720;

#pragma unroll
        for (int kk = 0; kk < 2; kk++) {
            uint32_t bh[4][2], bl[4][2];
#pragma unroll
            for (int p = 0; p < 2; p++) {
                uint32_t off = (uint32_t)(warpN + p * 16 + (lane & 15)) * 80u
                             + (uint32_t)kk * 32u + (uint32_t)(lane >> 4) * 16u;
                uint32_t r0, r1, r2, r3;
                ldmx4(r0, r1, r2, r3, bH + off);
                bh[p * 2][0] = r0; bh[p * 2 + 1][0] = r1;
                bh[p * 2][1] = r2; bh[p * 2 + 1][1] = r3;
                ldmx4(r0, r1, r2, r3, bL + off);
                bl[p * 2][0] = r0; bl[p * 2 + 1][0] = r1;
                bl[p * 2][1] = r2; bl[p * 2 + 1][1] = r3;
            }
#pragma unroll
            for (int fm = 0; fm < 4; fm++) {
                uint32_t off = (uint32_t)(warpM + fm * 16 + (lane & 15)) * 80u
                             + (uint32_t)kk * 32u + (uint32_t)(lane >> 4) * 16u;
                uint32_t ah[4], al[4];
                ldmx4(ah[0], ah[1], ah[2], ah[3], aH + off);
                ldmx4(al[0], al[1], al[2], al[3], aL + off);
#pragma unroll
                for (int fn = 0; fn < 4; fn++) {
                    mma_bf16(acc[fm][fn], ah, bh[fn]);
                    mma_bf16(acc[fm][fn], ah, bl[fn]);
                    mma_bf16(acc[fm][fn], al, bh[fn]);
                }
            }
        }
        __syncthreads();
    }

    const int gr = lane >> 2;
    const int gc = (lane & 3) * 2;
#pragma unroll
    for (int fm = 0; fm < 4; fm++) {
#pragma unroll
        for (int fn = 0; fn < 4; fn++) {
            int row0 = bm + warpM + fm * 16 + gr;
            int col  = bn + warpN + fn * 8 + gc;
#pragma unroll
            for (int half = 0; half < 2; half++) {
                int rr = row0 + half * 8;
                float v0 = acc[fm][fn][2 * half], v1 = acc[fm][fn][2 * half + 1];
                if (mode == 1 || col < 1024) {
                    *(float2*)&outQ[(size_t)rr * 1024 + col] = make_float2(v0, v1);
                } else {
                    int ckv = col - 1024;
                    int s = ckv >> 10;
                    int hh = (ckv & 1023) >> 6;
                    int d = ckv & 63;
                    int b = rr >> 11;
                    int n = rr & 2047;
                    size_t o = ((((size_t)s * B_ + b) * H_ + hh) * NXL_ + n + 1) * 64 + d;
                    *(float2*)&out2[o] = make_float2(v0, v1);
                }
            }
        }
    }
}

// ---------------------------------------------------------------------------
// Assemble K (rotated, (b,h,j,d)) and Vt ((b,h,d,j)); also out2 null row.
// Reads fresh k/v projections from out2 (written by fused GEMM epilogue).
// ---------------------------------------------------------------------------
__global__ void assemble_kv2(const float* __restrict__ xl,
                             const float* __restrict__ nullkv,
                             const float* __restrict__ rotk,
                             float* __restrict__ out2)
{
    __shared__ uint16_t svh[64][72], svl[64][72];
    const int j0 = blockIdx.x * 64;
    const int h = blockIdx.y, b = blockIdx.z;
    const int tid = threadIdx.x;
    const size_t bh = (size_t)b * H_ + h;

#pragma unroll
    for (int e = 0; e < 16; e++) {
        int idx = e * 256 + tid;
        int jl = idx >> 6;
        int j = j0 + jl;
        int d = idx & 63;
        int d2 = d ^ 32;

        float k0 = 0.f, k1 = 0.f, v0 = 0.f, pos = 0.f;
        if (j < M_) {
            size_t base = (((size_t)b * H_ + h) * M_ + j) * DH_;
            size_t voff = (size_t)B_ * H_ * M_ * DH_;
            k0 = xl[base + d];
            k1 = xl[base + d2];
            v0 = xl[voff + base + d];
            pos = rotk[(size_t)j * DH_ + d];
        } else if (j == M_) {
            k0 = nullkv[h * DH_ + d];
            k1 = nullkv[h * DH_ + d2];
            v0 = nullkv[H_ * DH_ + h * DH_ + d];
            pos = rotk[(size_t)j * DH_ + d];
            out2[(((size_t)0 * B_ + b) * H_ + h) * NXL_ * 64 + d] = k0;
            out2[(((size_t)1 * B_ + b) * H_ + h) * NXL_ * 64 + d] = v0;
        } else if (j < KV_) {
            int n = j - M_ - 1;
            size_t kbase = ((((size_t)0 * B_ + b) * H_ + h) * NXL_ + n + 1) * 64;
            size_t vbase = ((((size_t)1 * B_ + b) * H_ + h) * NXL_ + n + 1) * 64;
            k0 = out2[kbase + d];
            k1 = out2[kbase + d2];
            v0 = out2[vbase + d];
            pos = rotk[(size_t)j * DH_ + d];
        }
        float sn, cs;
        __sincosf(pos, &sn, &cs);
        float rot = (d < 32) ? -k1 : k1;
        float kr = k0 * cs + rot * sn;

        __nv_bfloat16 kh = __float2bfloat16(kr);
        __nv_bfloat16 kl = __float2bfloat16(kr - __bfloat162float(kh));
        size_t ko = (bh * KVP_ + j) * DH_ + d;
        g_kbh[ko] = kh;
        g_kbl[ko] = kl;

        __nv_bfloat16 vh = __float2bfloat16(v0);
        __nv_bfloat16 vl = __float2bfloat16(v0 - __bfloat162float(vh));
        svh[d][jl] = __bfloat16_as_ushort(vh);
        svl[d][jl] = __bfloat16_as_ushort(vl);
    }
    __syncthreads();

#pragma unroll
    for (int e = 0; e < 8; e++) {
        int idx = e * 256 + tid;
        int d = idx >> 5;
        int jj = (idx & 31) * 2;
        uint32_t ph = (uint32_t)svh[d][jj] | ((uint32_t)svh[d][jj + 1] << 16);
        uint32_t pl = (uint32_t)svl[d][jj] | ((uint32_t)svl[d][jj + 1] << 16);
        size_t o = (bh * DH_ + d) * KVP_ + j0 + jj;
        *(uint32_t*)&g_vth[o] = ph;
        *(uint32_t*)&g_vtl[o] = pl;
    }
}

// ---------------------------------------------------------------------------
// Flash attention: mma.sync 3-term S, 3-term PV, fp32 l (proven numerics).
// Q rotary+scale+split now done IN-KERNEL (prologue) from fp32 g_q.
// ---------------------------------------------------------------------------
#define FL_BUF   9216
#define FL_SMEM  (10 * FL_BUF)

__global__ __launch_bounds__(128, 2) void flash2(const float* __restrict__ rotq)
{
    extern __shared__ __align__(16) char fsm[];
    const int tid = threadIdx.x;
    const int lane = tid & 31;
    const int w = tid >> 5;
    const int bx = 31 - (int)blockIdx.x;
    const int h = blockIdx.y, b = blockIdx.z;
    const int i0 = bx * 64;
    const size_t bh = (size_t)b * H_ + h;

    uint32_t sb = smem_u32(fsm);

    const __nv_bfloat16* kh0 = g_kbh + bh * KVP_ * DH_;
    const __nv_bfloat16* kl0 = g_kbl + bh * KVP_ * DH_;
    const __nv_bfloat16* vh0 = g_vth + bh * DH_ * KVP_;
    const __nv_bfloat16* vl0 = g_vtl + bh * DH_ * KVP_;

    auto load_kv = [&](int t, int s) {
        int j0 = t * 64;
        uint32_t base = sb + 2 * FL_BUF + s * (4 * FL_BUF);
#pragma unroll
        for (int e = 0; e < 16; e++) {
            int lin = e * 128 + tid;
            int buf = lin >> 9;
            int idx = lin & 511;
            int r = idx >> 3, c = idx & 7;
            const __nv_bfloat16* gp;
            if (buf == 0)      gp = kh0 + (size_t)(j0 + r) * 64 + c * 8;
            else if (buf == 1) gp = kl0 + (size_t)(j0 + r) * 64 + c * 8;
            else if (buf == 2) gp = vh0 + (size_t)r * KVP_ + j0 + c * 8;
            else               gp = vl0 + (size_t)r * KVP_ + j0 + c * 8;
            CP_ASYNC16(base + buf * FL_BUF + r * 144 + c * 16, gp);
        }
    };

    load_kv(0, 0);
    CP_COMMIT();

    // --- Q prologue: load fp32 q, apply rotary+scale, split bf16, STS ---
    // (overlaps with the tile-0 cp.async in flight)
    {
        const float F = 0.18033688011112042f;   // 0.125 * log2(e)
        const float* qbase = g_q + ((size_t)b * N_ + i0) * INNER_ + h * DH_;
#pragma unroll
        for (int e = 0; e < 32; e++) {
            int idx = e * 128 + tid;         // 0..4095
            int r = idx >> 6, d = idx & 63;
            float q0 = qbase[(size_t)r * INNER_ + d];
            float q1 = qbase[(size_t)r * INNER_ + (d ^ 32)];
            float pos = rotq[(size_t)(i0 + r) * DH_ + d];
            float sn, cs;
            __sincosf(pos, &sn, &cs);
            float qr = (q0 * cs + ((d < 32) ? -q1 : q1) * sn) * F;
            __nv_bfloat16 qhv = __float2bfloat16(qr);
            __nv_bfloat16 qlv = __float2bfloat16(qr - __bfloat162float(qhv));
            uint32_t soff = (uint32_t)r * 144u + (uint32_t)d * 2u;
            *(uint16_t*)(fsm + soff) = __bfloat16_as_ushort(qhv);
            *(uint16_t*)(fsm + FL_BUF + soff) = __bfloat16_as_ushort(qlv);
        }
    }

    const int rpart = ((lane >> 3) & 1) * 8 + (lane & 7);
    const int cpart = (lane >> 4) * 8;
    const int gr = lane >> 2;
    const int gc = (lane & 3) * 2;

    uint32_t qh[4][4], ql[4][4];
    float oAcc[8][4];
    float mrow[2] = {-1e30f, -1e30f};
    float lrow[2] = {0.f, 0.f};
#pragma unroll
    for (int fn = 0; fn < 8; fn++)
#pragma unroll
        for (int e = 0; e < 4; e++) oAcc[fn][e] = 0.f;

    const int ntiles = bx + 10;
    for (int t = 0; t < ntiles; t++) {
        if (t > 0) __syncthreads();
        if (t + 1 < ntiles) { load_kv(t + 1, (t + 1) & 1); CP_COMMIT(); CP_WAIT1(); }
        else                { CP_WAIT0(); }
        __syncthreads();

        if (t == 0) {
            // Q fragments (STS above made visible by the barrier just executed)
#pragma unroll
            for (int kk = 0; kk < 4; kk++) {
                uint32_t off = (uint32_t)(w * 16 + (lane & 15)) * 144u
                             + (uint32_t)(kk * 16 + cpart) * 2u;
                ldmx4(qh[kk][0], qh[kk][1], qh[kk][2], qh[kk][3], sb + off);
                ldmx4(ql[kk][0], ql[kk][1], ql[kk][2], ql[kk][3], sb + FL_BUF + off);
            }
        }

        uint32_t stK = sb + 2 * FL_BUF + (t & 1) * (4 * FL_BUF);
        uint32_t stV = stK + 2 * FL_BUF;

        float sAcc[8][4];
#pragma unroll
        for (int fn = 0; fn < 8; fn++)
#pragma unroll
            for (int e = 0; e < 4; e++) sAcc[fn][e] = 0.f;

#pragma unroll
        for (int kk = 0; kk < 4; kk++) {
#pragma unroll
            for (int p = 0; p < 4; p++) {
                uint32_t off = (uint32_t)(p * 16 + rpart) * 144u
                             + (uint32_t)(kk * 16 + cpart) * 2u;
                uint32_t h0, h1, h2, h3, l0, l1, l2, l3;
                ldmx4(h0, h1, h2, h3, stK + off);
                ldmx4(l0, l1, l2, l3, stK + FL_BUF + off);
                uint32_t bh0[2] = {h0, h2}, bh1[2] = {h1, h3};
                uint32_t bl0[2] = {l0, l2}, bl1[2] = {l1, l3};
                mma_bf16(sAcc[2 * p],     qh[kk], bh0);
                mma_bf16(sAcc[2 * p],     qh[kk], bl0);
                mma_bf16(sAcc[2 * p],     ql[kk], bh0);
                mma_bf16(sAcc[2 * p + 1], qh[kk], bh1);
                mma_bf16(sAcc[2 * p + 1], qh[kk], bl1);
                mma_bf16(sAcc[2 * p + 1], ql[kk], bh1);
            }
        }

        if (t >= ntiles - 2) {
            int j0 = t * 64;
#pragma unroll
            for (int fn = 0; fn < 8; fn++) {
#pragma unroll
                for (int e = 0; e < 4; e++) {
                    int gj = j0 + fn * 8 + gc + (e & 1);
                    int gi = i0 + w * 16 + gr + (e >> 1) * 8;
                    if (gj > gi + (KV_ - N_)) sAcc[fn][e] = -1e30f;
                }
            }
        }

        float mt0 = -1e30f, mt1 = -1e30f;
#pragma unroll
        for (int fn = 0; fn < 8; fn++) {
            mt0 = fmaxf(mt0, fmaxf(sAcc[fn][0], sAcc[fn][1]));
            mt1 = fmaxf(mt1, fmaxf(sAcc[fn][2], sAcc[fn][3]));
        }
        mt0 = fmaxf(mt0, __shfl_xor_sync(0xffffffffu, mt0, 1));
        mt0 = fmaxf(mt0, __shfl_xor_sync(0xffffffffu, mt0, 2));
        mt1 = fmaxf(mt1, __shfl_xor_sync(0xffffffffu, mt1, 1));
        mt1 = fmaxf(mt1, __shfl_xor_sync(0xffffffffu, mt1, 2));

        float mn0 = fmaxf(mrow[0], mt0), mn1 = fmaxf(mrow[1], mt1);
        float al0 = exp2fast(mrow[0] - mn0), al1 = exp2fast(mrow[1] - mn1);
        mrow[0] = mn0; mrow[1] = mn1;

        float ls0 = 0.f, ls1 = 0.f;
#pragma unroll
        for (int fn = 0; fn < 8; fn++) {
            sAcc[fn][0] = exp2fast(sAcc[fn][0] - mn0);
            sAcc[fn][1] = exp2fast(sAcc[fn][1] - mn0);
            sAcc[fn][2] = exp2fast(sAcc[fn][2] - mn1);
            sAcc[fn][3] = exp2fast(sAcc[fn][3] - mn1);
            ls0 += sAcc[fn][0] + sAcc[fn][1];
            ls1 += sAcc[fn][2] + sAcc[fn][3];
        }
        ls0 += __shfl_xor_sync(0xffffffffu, ls0, 1);
        ls0 += __shfl_xor_sync(0xffffffffu, ls0, 2);
        ls1 += __shfl_xor_sync(0xffffffffu, ls1, 1);
        ls1 += __shfl_xor_sync(0xffffffffu, ls1, 2);
        lrow[0] = lrow[0] * al0 + ls0;
        lrow[1] = lrow[1] * al1 + ls1;
#pragma unroll
        for (int fn = 0; fn < 8; fn++) {
            oAcc[fn][0] *= al0; oAcc[fn][1] *= al0;
            oAcc[fn][2] *= al1; oAcc[fn][3] *= al1;
        }

        uint32_t ph[4][4], pl[4][4];
#pragma unroll
        for (int kk = 0; kk < 4; kk++) {
#pragma unroll
            for (int half = 0; half < 2; half++) {
                const float* src = sAcc[2 * kk + half];
                float x0 = src[0], x1 = src[1], x2 = src[2], x3 = src[3];
                uint32_t hA = packbf2(x0, x1);
                uint32_t hB = packbf2(x2, x3);
                __nv_bfloat162 hA2 = *(__nv_bfloat162*)&hA;
                __nv_bfloat162 hB2 = *(__nv_bfloat162*)&hB;
                uint32_t lA = packbf2(x0 - __bfloat162float(hA2.x),
                                      x1 - __bfloat162float(hA2.y));
                uint32_t lB = packbf2(x2 - __bfloat162float(hB2.x),
                                      x3 - __bfloat162float(hB2.y));
                ph[kk][half * 2 + 0] = hA;
                ph[kk][half * 2 + 1] = hB;
                pl[kk][half * 2 + 0] = lA;
                pl[kk][half * 2 + 1] = lB;
            }
        }

#pragma unroll
        for (int kk = 0; kk < 4; kk++) {
#pragma unroll
            for (int p = 0; p < 4; p++) {
                uint32_t off = (uint32_t)(p * 16 + rpart) * 144u
                             + (uint32_t)(kk * 16 + cpart) * 2u;
                uint32_t h0, h1, h2, h3, l0, l1, l2, l3;
                ldmx4(h0, h1, h2, h3, stV + off);
                ldmx4(l0, l1, l2, l3, stV + FL_BUF + off);
                uint32_t bh0[2] = {h0, h2}, bh1[2] = {h1, h3};
                uint32_t bl0[2] = {l0, l2}, bl1[2] = {l1, l3};
                mma_bf16(oAcc[2 * p],     ph[kk], bh0);
                mma_bf16(oAcc[2 * p],     ph[kk], bl0);
                mma_bf16(oAcc[2 * p],     pl[kk], bh0);
                mma_bf16(oAcc[2 * p + 1], ph[kk], bh1);
                mma_bf16(oAcc[2 * p + 1], ph[kk], bl1);
                mma_bf16(oAcc[2 * p + 1], pl[kk], bh1);
            }
        }
    }

    float inv0 = 1.f / lrow[0];
    float inv1 = 1.f / lrow[1];
    int gi0 = i0 + w * 16 + gr;
#pragma unroll
    for (int fn = 0; fn < 8; fn++) {
        int col = h * DH_ + fn * 8 + gc;
        {
            float o0 = oAcc[fn][0] * inv0, o1 = oAcc[fn][1] * inv0;
            uint32_t hi = packbf2(o0, o1);
            __nv_bfloat162 h2 = *(__nv_bfloat162*)&hi;
            uint32_t lo = packbf2(o0 - __bfloat162float(h2.x), o1 - __bfloat162float(h2.y));
            size_t o = ((size_t)b * N_ + gi0) * INNER_ + col;
            *(uint32_t*)&g_ah[o] = hi;
            *(uint32_t*)&g_al[o] = lo;
        }
        {
            float o0 = oAcc[fn][2] * inv1, o1 = oAcc[fn][3] * inv1;
            uint32_t hi = packbf2(o0, o1);
            __nv_bfloat162 h2 = *(__nv_bfloat162*)&hi;
            uint32_t lo = packbf2(o0 - __bfloat162float(h2.x), o1 - __bfloat162float(h2.y));
            size_t o = ((size_t)b * N_ + gi0 + 8) * INNER_ + col;
            *(uint32_t*)&g_ah[o] = hi;
            *(uint32_t*)&g_al[o] = lo;
        }
    }
}

// ---------------------------------------------------------------------------
// Launch
// ---------------------------------------------------------------------------
extern "C" void kernel_launch(void* const* d_in, const int* in_sizes, int n_in,
                              void* d_out, int out_size)
{
    const float* x    = (const float*)d_in[0];
    const float* rotq = (const float*)d_in[1];
    const float* rotk = (const float*)d_in[2];
    const float* xl   = (const float*)d_in[3];
    const float* Wq   = (const float*)d_in[4];
    const float* Wkv  = (const float*)d_in[5];
    const float* Wout = (const float*)d_in[6];
    const float* nkv  = (const float*)d_in[7];

    float* out1 = (float*)d_out;
    float* out2 = out1 + (size_t)B_ * N_ * INNER_;

    void *pq, *pxh, *pxl, *pah, *pal, *pwh, *pwl;
    cudaGetSymbolAddress(&pq, g_q);
    cudaGetSymbolAddress(&pxh, g_xh);
    cudaGetSymbolAddress(&pxl, g_xl);
    cudaGetSymbolAddress(&pah, g_ah);
    cudaGetSymbolAddress(&pal, g_al);
    cudaGetSymbolAddress(&pwh, g_wh);
    cudaGetSymbolAddress(&pwl, g_wl);

    __nv_bfloat16* xh = (__nv_bfloat16*)pxh;
    __nv_bfloat16* xlo = (__nv_bfloat16*)pxl;
    __nv_bfloat16* ah = (__nv_bfloat16*)pah;
    __nv_bfloat16* al = (__nv_bfloat16*)pal;
    __nv_bfloat16* wh = (__nv_bfloat16*)pwh;
    __nv_bfloat16* wl = (__nv_bfloat16*)pwl;

    cudaFuncSetAttribute(gemm_mma3, cudaFuncAttributeMaxDynamicSharedMemorySize, GEMM_SMEM);
    cudaFuncSetAttribute(flash2, cudaFuncAttributeMaxDynamicSharedMemorySize, FL_SMEM);

    // 1) conversions + weight prep (single merged transpose launch)
    {
        size_t n4 = (size_t)B_ * N_ * DIM_ / 4;
        convert_split<<<(unsigned)((n4 + 255) / 256), 256>>>(x, xh, xlo, n4);
    }
    transpose_split_all<<<dim3(128, 32), dim3(32, 8)>>>(Wq, Wkv, Wout);

    // 2) fused q+kv projection (N=3072): q -> g_q; kv -> out2 rows 1..N
    gemm_mma3<<<dim3(3072 / 128, 4096 / 128), 256, GEMM_SMEM>>>(
        xh, xlo, wh, wl, (float*)pq, out2, 0);

    // 3) K/V assembly (reads kv from out2; writes null row)
    assemble_kv2<<<dim3(KVP_ / 64, H_, B_), 256>>>(xl, nkv, rotk, out2);

    // 4) flash attention (Q rotary in-kernel) -> g_ah/g_al
    flash2<<<dim3(32, H_, B_), 128, FL_SMEM>>>(rotq);

    // 5) output projection
    gemm_mma3<<<dim3(1024 / 128, 4096 / 128), 256, GEMM_SMEM>>>(
        ah, al, wh + 3u * (1u << 20), wl + 3u * (1u << 20), out1, nullptr, 1);
}

// round 17
// speedup vs baseline: 1.4994x; 1.0060x over previous
#include <cuda_runtime.h>
#include <cuda_bf16.h>
#include <math.h>
#include <stdint.h>

// Problem constants
#define B_      2
#define N_      2048
#define DIM_    1024
#define H_      16
#define DH_     64
#define M_      512
#define INNER_  1024
#define KV_     2561      // M + 1 + N
#define NXL_    2049      // 1 + N
#define KVP_    2624      // KV padded to 41*64

// ---------------------------------------------------------------------------
// Device scratch
// ---------------------------------------------------------------------------
__device__ __align__(16) float g_q   [(size_t)B_ * N_ * INNER_];

__device__ __align__(256) __nv_bfloat16 g_xh[(size_t)B_ * N_ * DIM_];
__device__ __align__(256) __nv_bfloat16 g_xl[(size_t)B_ * N_ * DIM_];
__device__ __align__(256) __nv_bfloat16 g_ah[(size_t)B_ * N_ * INNER_];
__device__ __align__(256) __nv_bfloat16 g_al[(size_t)B_ * N_ * INNER_];
__device__ __align__(256) __nv_bfloat16 g_wh[(size_t)4 * 1024 * 1024];
__device__ __align__(256) __nv_bfloat16 g_wl[(size_t)4 * 1024 * 1024];

// attention K/V operands, bf16 hi/lo
__device__ __align__(256) __nv_bfloat16 g_kbh[(size_t)B_ * H_ * KVP_ * DH_];
__device__ __align__(256) __nv_bfloat16 g_kbl[(size_t)B_ * H_ * KVP_ * DH_];
__device__ __align__(256) __nv_bfloat16 g_vth[(size_t)B_ * H_ * DH_ * KVP_];
__device__ __align__(256) __nv_bfloat16 g_vtl[(size_t)B_ * H_ * DH_ * KVP_];

// ---------------------------------------------------------------------------
// PTX helpers — base sm_103-safe subset
// ---------------------------------------------------------------------------
__device__ __forceinline__ uint32_t smem_u32(const void* p) {
    uint32_t a;
    asm("{ .reg .u64 t; cvta.to.shared.u64 t, %1; cvt.u32.u64 %0, t; }" : "=r"(a) : "l"(p));
    return a;
}

#define CP_ASYNC16(smem, gptr) \
    asm volatile("cp.async.cg.shared.global [%0], [%1], 16;" :: "r"(smem), "l"(gptr) : "memory")
#define CP_COMMIT() asm volatile("cp.async.commit_group;" ::: "memory")
#define CP_WAIT0()  asm volatile("cp.async.wait_group 0;" ::: "memory")
#define CP_WAIT1()  asm volatile("cp.async.wait_group 1;" ::: "memory")

__device__ __forceinline__ void ldmx4(uint32_t& r0, uint32_t& r1, uint32_t& r2, uint32_t& r3,
                                      uint32_t addr) {
    asm volatile("ldmatrix.sync.aligned.m8n8.x4.shared.b16 {%0,%1,%2,%3}, [%4];"
                 : "=r"(r0), "=r"(r1), "=r"(r2), "=r"(r3) : "r"(addr));
}

__device__ __forceinline__ void mma_bf16(float* c, const uint32_t* a, const uint32_t* b) {
    asm volatile(
        "mma.sync.aligned.m16n8k16.row.col.f32.bf16.bf16.f32 "
        "{%0,%1,%2,%3}, {%4,%5,%6,%7}, {%8,%9}, {%0,%1,%2,%3};"
        : "+f"(c[0]), "+f"(c[1]), "+f"(c[2]), "+f"(c[3])
        : "r"(a[0]), "r"(a[1]), "r"(a[2]), "r"(a[3]), "r"(b[0]), "r"(b[1]));
}

// exp2 without MUFU (attention domain x <= 0)
__device__ __forceinline__ float exp2fast(float x) {
    x = fmaxf(x, -126.0f);
    float t = x + 12582912.0f;
    int k = __float_as_int(t) - 0x4b400000;
    float f = x - (t - 12582912.0f);
    float p = 1.3333558e-3f;
    p = fmaf(p, f, 9.6181291e-3f);
    p = fmaf(p, f, 5.5504109e-2f);
    p = fmaf(p, f, 2.4022651e-1f);
    p = fmaf(p, f, 6.9314718e-1f);
    p = fmaf(p, f, 1.0f);
    return __int_as_float(__float_as_int(p) + (k << 23));
}

__device__ __forceinline__ uint32_t packbf2(float a, float b) {
    __nv_bfloat162 t = __floats2bfloat162_rn(a, b);
    return *(uint32_t*)&t;
}
__device__ __forceinline__ uint32_t pack_bf2u(__nv_bfloat16 a, __nv_bfloat16 b) {
    return (uint32_t)__bfloat16_as_ushort(a) | ((uint32_t)__bfloat16_as_ushort(b) << 16);
}

// ---------------------------------------------------------------------------
// fp32 -> bf16 hi/lo split
// ---------------------------------------------------------------------------
__global__ void convert_split(const float* __restrict__ in,
                              __nv_bfloat16* __restrict__ hi,
                              __nv_bfloat16* __restrict__ lo, size_t n4)
{
    size_t i = (size_t)blockIdx.x * blockDim.x + threadIdx.x;
    if (i >= n4) return;
    float4 v = ((const float4*)in)[i];
    __nv_bfloat16 h0 = __float2bfloat16(v.x), h1 = __float2bfloat16(v.y);
    __nv_bfloat16 h2 = __float2bfloat16(v.z), h3 = __float2bfloat16(v.w);
    __nv_bfloat16 l0 = __float2bfloat16(v.x - __bfloat162float(h0));
    __nv_bfloat16 l1 = __float2bfloat16(v.y - __bfloat162float(h1));
    __nv_bfloat16 l2 = __float2bfloat16(v.z - __bfloat162float(h2));
    __nv_bfloat16 l3 = __float2bfloat16(v.w - __bfloat162float(h3));
    ((uint2*)hi)[i] = make_uint2(pack_bf2u(h0, h1), pack_bf2u(h2, h3));
    ((uint2*)lo)[i] = make_uint2(pack_bf2u(l0, l1), pack_bf2u(l2, l3));
}

// Merged weight transpose+split: bx<32 -> Wq; 32<=bx<96 -> Wkv; bx>=96 -> Wout
__global__ void transpose_split_all(const float* __restrict__ Wq,
                                    const float* __restrict__ Wkv,
                                    const float* __restrict__ Wout)
{
    __shared__ float s[32][33];
    int bx = blockIdx.x;
    const float* in;
    __nv_bfloat16 *hi, *lo;
    int Ncols, n0;
    if (bx < 32)      { in = Wq;   hi = g_wh;                lo = g_wl;                Ncols = 1024; n0 = bx * 32; }
    else if (bx < 96) { in = Wkv;  hi = g_wh + (1u << 20);   lo = g_wl + (1u << 20);   Ncols = 2048; n0 = (bx - 32) * 32; }
    else              { in = Wout; hi = g_wh + 3u * (1u << 20); lo = g_wl + 3u * (1u << 20); Ncols = 1024; n0 = (bx - 96) * 32; }
    int k0 = blockIdx.y * 32;
    int tx = threadIdx.x, ty = threadIdx.y;  // 32 x 8
#pragma unroll
    for (int r = 0; r < 4; r++)
        s[ty + r * 8][tx] = in[(size_t)(k0 + ty + r * 8) * Ncols + n0 + tx];
    __syncthreads();
#pragma unroll
    for (int r = 0; r < 4; r++) {
        int row = ty + r * 8;
        float v = s[tx][row];
        __nv_bfloat16 h = __float2bfloat16(v);
        __nv_bfloat16 l = __float2bfloat16(v - __bfloat162float(h));
        size_t o = (size_t)(n0 + row) * 1024 + k0 + tx;
        hi[o] = h;
        lo[o] = l;
    }
}

// ---------------------------------------------------------------------------
// GEMM via mma.sync: CTA 128x128, 256 threads (8 warps 2m x 4n), warp 64x32,
// BK=32, 2-stage cp.async, occupancy 2. 3-term bf16 split (proven config).
// mode 0: fused qkv (grid x covers N=3072): col<1024 -> outQ (g_q, pitch 1024),
//         col>=1024 -> out2 scatter ONLY (next_xl rows 1..N)
// mode 1: plain write to outQ, pitch 1024
// ---------------------------------------------------------------------------
#define STAGE_BYTES 40960
#define GEMM_SMEM   (2 * STAGE_BYTES + 128)

__global__ __launch_bounds__(256, 2) void gemm_mma3(
    const __nv_bfloat16* __restrict__ Ah, const __nv_bfloat16* __restrict__ Al,
    const __nv_bfloat16* __restrict__ Bh, const __nv_bfloat16* __restrict__ Bl,
    float* __restrict__ outQ, float* __restrict__ out2, int mode)
{
    extern __shared__ char dsm[];
    const int tid = threadIdx.x;
    const int lane = tid & 31;
    const int wid = tid >> 5;
    const int bm = blockIdx.y * 128, bn = blockIdx.x * 128;
    const int warpM = (wid >> 2) * 64;
    const int warpN = (wid & 3) * 32;

    uint32_t sb = (smem_u32(dsm) + 127) & ~127u;

    auto load_stage = [&](int chunk, int stage) {
        const int k0 = chunk * 32;
        uint32_t base = sb + stage * STAGE_BYTES;
#pragma unroll
        for (int e = 0; e < 8; e++) {
            int lin = e * 256 + tid;
            int buf = lin >> 9;
            int idx = lin & 511;
            int r = idx >> 2;
            int c = idx & 3;
            uint32_t soff = (uint32_t)buf * 10240u + (uint32_t)r * 80u + (uint32_t)c * 16u;
            const __nv_bfloat16* gp;
            if (buf == 0)      gp = Ah + (size_t)(bm + r) * 1024 + k0;
            else if (buf == 1) gp = Al + (size_t)(bm + r) * 1024 + k0;
            else if (buf == 2) gp = Bh + (size_t)(bn + r) * 1024 + k0;
            else               gp = Bl + (size_t)(bn + r) * 1024 + k0;
            CP_ASYNC16(base + soff, gp + c * 8);
        }
        CP_COMMIT();
    };

    float acc[4][4][4];
#pragma unroll
    for (int i = 0; i < 4; i++)
#pragma unroll
        for (int j = 0; j < 4; j++)
#pragma unroll
            for (int k = 0; k < 4; k++) acc[i][j][k] = 0.f;

    load_stage(0, 0);

    const int NC = 32;
    for (int ch = 0; ch < NC; ch++) {
        int s = ch & 1;
        if (ch + 1 < NC) { load_stage(ch + 1, s ^ 1); CP_WAIT1(); }
        else             { CP_WAIT0(); }
        __syncthreads();

        uint32_t st = sb + s * STAGE_BYTES;
        uint32_t aH = st, aL = st + 10240, bH = st + 20480, bL = st + 30720;

#pragma unroll
        for (int kk = 0; kk < 2; kk++) {
            uint32_t bh[4][2], bl[4][2];
#pragma unroll
            for (int p = 0; p < 2; p++) {
                uint32_t off = (uint32_t)(warpN + p * 16 + (lane & 15)) * 80u
                             + (uint32_t)kk * 32u + (uint32_t)(lane >> 4) * 16u;
                uint32_t r0, r1, r2, r3;
                ldmx4(r0, r1, r2, r3, bH + off);
                bh[p * 2][0] = r0; bh[p * 2 + 1][0] = r1;
                bh[p * 2][1] = r2; bh[p * 2 + 1][1] = r3;
                ldmx4(r0, r1, r2, r3, bL + off);
                bl[p * 2][0] = r0; bl[p * 2 + 1][0] = r1;
                bl[p * 2][1] = r2; bl[p * 2 + 1][1] = r3;
            }
#pragma unroll
            for (int fm = 0; fm < 4; fm++) {
                uint32_t off = (uint32_t)(warpM + fm * 16 + (lane & 15)) * 80u
                             + (uint32_t)kk * 32u + (uint32_t)(lane >> 4) * 16u;
                uint32_t ah[4], al[4];
                ldmx4(ah[0], ah[1], ah[2], ah[3], aH + off);
                ldmx4(al[0], al[1], al[2], al[3], aL + off);
#pragma unroll
                for (int fn = 0; fn < 4; fn++) {
                    mma_bf16(acc[fm][fn], ah, bh[fn]);
                    mma_bf16(acc[fm][fn], ah, bl[fn]);
                    mma_bf16(acc[fm][fn], al, bh[fn]);
                }
            }
        }
        __syncthreads();
    }

    const int gr = lane >> 2;
    const int gc = (lane & 3) * 2;
#pragma unroll
    for (int fm = 0; fm < 4; fm++) {
#pragma unroll
        for (int fn = 0; fn < 4; fn++) {
            int row0 = bm + warpM + fm * 16 + gr;
            int col  = bn + warpN + fn * 8 + gc;
#pragma unroll
            for (int half = 0; half < 2; half++) {
                int rr = row0 + half * 8;
                float v0 = acc[fm][fn][2 * half], v1 = acc[fm][fn][2 * half + 1];
                if (mode == 1 || col < 1024) {
                    *(float2*)&outQ[(size_t)rr * 1024 + col] = make_float2(v0, v1);
                } else {
                    int ckv = col - 1024;
                    int s = ckv >> 10;
                    int hh = (ckv & 1023) >> 6;
                    int d = ckv & 63;
                    int b = rr >> 11;
                    int n = rr & 2047;
                    size_t o = ((((size_t)s * B_ + b) * H_ + hh) * NXL_ + n + 1) * 64 + d;
                    *(float2*)&out2[o] = make_float2(v0, v1);
                }
            }
        }
    }
}

// ---------------------------------------------------------------------------
// Assemble K (rotated, (b,h,j,d)) and Vt ((b,h,d,j)); also out2 null row.
// Vectorized: each thread handles a pair of consecutive d (float2 loads,
// uint32 bf16x2 stores). Reads fresh k/v projections from out2.
// ---------------------------------------------------------------------------
__global__ void assemble_kv2(const float* __restrict__ xl,
                             const float* __restrict__ nullkv,
                             const float* __restrict__ rotk,
                             float* __restrict__ out2)
{
    __shared__ uint16_t svh[64][72], svl[64][72];
    const int j0 = blockIdx.x * 64;
    const int h = blockIdx.y, b = blockIdx.z;
    const int tid = threadIdx.x;
    const size_t bh = (size_t)b * H_ + h;

#pragma unroll
    for (int e = 0; e < 8; e++) {
        int idx = e * 256 + tid;          // 0..2047
        int jl = idx >> 5;                // 0..63
        int dp = (idx & 31) * 2;          // even d: 0,2,..,62
        int j = j0 + jl;
        int dq = dp ^ 32;                 // rotary partner pair base

        float2 ka = make_float2(0.f, 0.f), kb = make_float2(0.f, 0.f);
        float2 va = make_float2(0.f, 0.f), pp = make_float2(0.f, 0.f);
        if (j < M_) {
            size_t base = (((size_t)b * H_ + h) * M_ + j) * DH_;
            size_t voff = (size_t)B_ * H_ * M_ * DH_;
            ka = *(const float2*)&xl[base + dp];
            kb = *(const float2*)&xl[base + dq];
            va = *(const float2*)&xl[voff + base + dp];
            pp = *(const float2*)&rotk[(size_t)j * DH_ + dp];
        } else if (j == M_) {
            ka = *(const float2*)&nullkv[h * DH_ + dp];
            kb = *(const float2*)&nullkv[h * DH_ + dq];
            va = *(const float2*)&nullkv[H_ * DH_ + h * DH_ + dp];
            pp = *(const float2*)&rotk[(size_t)j * DH_ + dp];
            *(float2*)&out2[(((size_t)0 * B_ + b) * H_ + h) * NXL_ * 64 + dp] = ka;
            *(float2*)&out2[(((size_t)1 * B_ + b) * H_ + h) * NXL_ * 64 + dp] = va;
        } else if (j < KV_) {
            int n = j - M_ - 1;
            size_t kbase = ((((size_t)0 * B_ + b) * H_ + h) * NXL_ + n + 1) * 64;
            size_t vbase = ((((size_t)1 * B_ + b) * H_ + h) * NXL_ + n + 1) * 64;
            ka = *(const float2*)&out2[kbase + dp];
            kb = *(const float2*)&out2[kbase + dq];
            va = *(const float2*)&out2[vbase + dp];
            pp = *(const float2*)&rotk[(size_t)j * DH_ + dp];
        }

        float sn0, cs0, sn1, cs1;
        __sincosf(pp.x, &sn0, &cs0);
        __sincosf(pp.y, &sn1, &cs1);
        float sgn = (dp < 32) ? -1.f : 1.f;
        float kr0 = ka.x * cs0 + sgn * kb.x * sn0;
        float kr1 = ka.y * cs1 + sgn * kb.y * sn1;

        uint32_t khp = packbf2(kr0, kr1);
        __nv_bfloat162 kh2 = *(__nv_bfloat162*)&khp;
        uint32_t klp = packbf2(kr0 - __bfloat162float(kh2.x),
                               kr1 - __bfloat162float(kh2.y));
        size_t ko = (bh * KVP_ + j) * DH_ + dp;
        *(uint32_t*)&g_kbh[ko] = khp;
        *(uint32_t*)&g_kbl[ko] = klp;

        uint32_t vhp = packbf2(va.x, va.y);
        __nv_bfloat162 vh2 = *(__nv_bfloat162*)&vhp;
        uint32_t vlp = packbf2(va.x - __bfloat162float(vh2.x),
                               va.y - __bfloat162float(vh2.y));
        svh[dp][jl]     = (uint16_t)(vhp & 0xffff);
        svh[dp + 1][jl] = (uint16_t)(vhp >> 16);
        svl[dp][jl]     = (uint16_t)(vlp & 0xffff);
        svl[dp + 1][jl] = (uint16_t)(vlp >> 16);
    }
    __syncthreads();

#pragma unroll
    for (int e = 0; e < 8; e++) {
        int idx = e * 256 + tid;
        int d = idx >> 5;
        int jj = (idx & 31) * 2;
        uint32_t ph = (uint32_t)svh[d][jj] | ((uint32_t)svh[d][jj + 1] << 16);
        uint32_t pl = (uint32_t)svl[d][jj] | ((uint32_t)svl[d][jj + 1] << 16);
        size_t o = (bh * DH_ + d) * KVP_ + j0 + jj;
        *(uint32_t*)&g_vth[o] = ph;
        *(uint32_t*)&g_vtl[o] = pl;
    }
}

// ---------------------------------------------------------------------------
// Flash attention: mma.sync 3-term S, 3-term PV, fp32 l (proven numerics).
// Q rotary+scale+split done IN-KERNEL (prologue) from fp32 g_q.
// ---------------------------------------------------------------------------
#define FL_BUF   9216
#define FL_SMEM  (10 * FL_BUF)

__global__ __launch_bounds__(128, 2) void flash2(const float* __restrict__ rotq)
{
    extern __shared__ __align__(16) char fsm[];
    const int tid = threadIdx.x;
    const int lane = tid & 31;
    const int w = tid >> 5;
    const int bx = 31 - (int)blockIdx.x;
    const int h = blockIdx.y, b = blockIdx.z;
    const int i0 = bx * 64;
    const size_t bh = (size_t)b * H_ + h;

    uint32_t sb = smem_u32(fsm);

    const __nv_bfloat16* kh0 = g_kbh + bh * KVP_ * DH_;
    const __nv_bfloat16* kl0 = g_kbl + bh * KVP_ * DH_;
    const __nv_bfloat16* vh0 = g_vth + bh * DH_ * KVP_;
    const __nv_bfloat16* vl0 = g_vtl + bh * DH_ * KVP_;

    auto load_kv = [&](int t, int s) {
        int j0 = t * 64;
        uint32_t base = sb + 2 * FL_BUF + s * (4 * FL_BUF);
#pragma unroll
        for (int e = 0; e < 16; e++) {
            int lin = e * 128 + tid;
            int buf = lin >> 9;
            int idx = lin & 511;
            int r = idx >> 3, c = idx & 7;
            const __nv_bfloat16* gp;
            if (buf == 0)      gp = kh0 + (size_t)(j0 + r) * 64 + c * 8;
            else if (buf == 1) gp = kl0 + (size_t)(j0 + r) * 64 + c * 8;
            else if (buf == 2) gp = vh0 + (size_t)r * KVP_ + j0 + c * 8;
            else               gp = vl0 + (size_t)r * KVP_ + j0 + c * 8;
            CP_ASYNC16(base + buf * FL_BUF + r * 144 + c * 16, gp);
        }
    };

    load_kv(0, 0);
    CP_COMMIT();

    // --- Q prologue: load fp32 q, apply rotary+scale, split bf16, STS ---
    {
        const float F = 0.18033688011112042f;   // 0.125 * log2(e)
        const float* qbase = g_q + ((size_t)b * N_ + i0) * INNER_ + h * DH_;
#pragma unroll
        for (int e = 0; e < 32; e++) {
            int idx = e * 128 + tid;         // 0..4095
            int r = idx >> 6, d = idx & 63;
            float q0 = qbase[(size_t)r * INNER_ + d];
            float q1 = qbase[(size_t)r * INNER_ + (d ^ 32)];
            float pos = rotq[(size_t)(i0 + r) * DH_ + d];
            float sn, cs;
            __sincosf(pos, &sn, &cs);
            float qr = (q0 * cs + ((d < 32) ? -q1 : q1) * sn) * F;
            __nv_bfloat16 qhv = __float2bfloat16(qr);
            __nv_bfloat16 qlv = __float2bfloat16(qr - __bfloat162float(qhv));
            uint32_t soff = (uint32_t)r * 144u + (uint32_t)d * 2u;
            *(uint16_t*)(fsm + soff) = __bfloat16_as_ushort(qhv);
            *(uint16_t*)(fsm + FL_BUF + soff) = __bfloat16_as_ushort(qlv);
        }
    }

    const int rpart = ((lane >> 3) & 1) * 8 + (lane & 7);
    const int cpart = (lane >> 4) * 8;
    const int gr = lane >> 2;
    const int gc = (lane & 3) * 2;

    uint32_t qh[4][4], ql[4][4];
    float oAcc[8][4];
    float mrow[2] = {-1e30f, -1e30f};
    float lrow[2] = {0.f, 0.f};
#pragma unroll
    for (int fn = 0; fn < 8; fn++)
#pragma unroll
        for (int e = 0; e < 4; e++) oAcc[fn][e] = 0.f;

    const int ntiles = bx + 10;
    for (int t = 0; t < ntiles; t++) {
        if (t > 0) __syncthreads();
        if (t + 1 < ntiles) { load_kv(t + 1, (t + 1) & 1); CP_COMMIT(); CP_WAIT1(); }
        else                { CP_WAIT0(); }
        __syncthreads();

        if (t == 0) {
#pragma unroll
            for (int kk = 0; kk < 4; kk++) {
                uint32_t off = (uint32_t)(w * 16 + (lane & 15)) * 144u
                             + (uint32_t)(kk * 16 + cpart) * 2u;
                ldmx4(qh[kk][0], qh[kk][1], qh[kk][2], qh[kk][3], sb + off);
                ldmx4(ql[kk][0], ql[kk][1], ql[kk][2], ql[kk][3], sb + FL_BUF + off);
            }
        }

        uint32_t stK = sb + 2 * FL_BUF + (t & 1) * (4 * FL_BUF);
        uint32_t stV = stK + 2 * FL_BUF;

        float sAcc[8][4];
#pragma unroll
        for (int fn = 0; fn < 8; fn++)
#pragma unroll
            for (int e = 0; e < 4; e++) sAcc[fn][e] = 0.f;

#pragma unroll
        for (int kk = 0; kk < 4; kk++) {
#pragma unroll
            for (int p = 0; p < 4; p++) {
                uint32_t off = (uint32_t)(p * 16 + rpart) * 144u
                             + (uint32_t)(kk * 16 + cpart) * 2u;
                uint32_t h0, h1, h2, h3, l0, l1, l2, l3;
                ldmx4(h0, h1, h2, h3, stK + off);
                ldmx4(l0, l1, l2, l3, stK + FL_BUF + off);
                uint32_t bh0[2] = {h0, h2}, bh1[2] = {h1, h3};
                uint32_t bl0[2] = {l0, l2}, bl1[2] = {l1, l3};
                mma_bf16(sAcc[2 * p],     qh[kk], bh0);
                mma_bf16(sAcc[2 * p],     qh[kk], bl0);
                mma_bf16(sAcc[2 * p],     ql[kk], bh0);
                mma_bf16(sAcc[2 * p + 1], qh[kk], bh1);
                mma_bf16(sAcc[2 * p + 1], qh[kk], bl1);
                mma_bf16(sAcc[2 * p + 1], ql[kk], bh1);
            }
        }

        if (t >= ntiles - 2) {
            int j0 = t * 64;
#pragma unroll
            for (int fn = 0; fn < 8; fn++) {
#pragma unroll
                for (int e = 0; e < 4; e++) {
                    int gj = j0 + fn * 8 + gc + (e & 1);
                    int gi = i0 + w * 16 + gr + (e >> 1) * 8;
                    if (gj > gi + (KV_ - N_)) sAcc[fn][e] = -1e30f;
                }
            }
        }

        float mt0 = -1e30f, mt1 = -1e30f;
#pragma unroll
        for (int fn = 0; fn < 8; fn++) {
            mt0 = fmaxf(mt0, fmaxf(sAcc[fn][0], sAcc[fn][1]));
            mt1 = fmaxf(mt1, fmaxf(sAcc[fn][2], sAcc[fn][3]));
        }
        mt0 = fmaxf(mt0, __shfl_xor_sync(0xffffffffu, mt0, 1));
        mt0 = fmaxf(mt0, __shfl_xor_sync(0xffffffffu, mt0, 2));
        mt1 = fmaxf(mt1, __shfl_xor_sync(0xffffffffu, mt1, 1));
        mt1 = fmaxf(mt1, __shfl_xor_sync(0xffffffffu, mt1, 2));

        float mn0 = fmaxf(mrow[0], mt0), mn1 = fmaxf(mrow[1], mt1);
        float al0 = exp2fast(mrow[0] - mn0), al1 = exp2fast(mrow[1] - mn1);
        mrow[0] = mn0; mrow[1] = mn1;

        float ls0 = 0.f, ls1 = 0.f;
#pragma unroll
        for (int fn = 0; fn < 8; fn++) {
            sAcc[fn][0] = exp2fast(sAcc[fn][0] - mn0);
            sAcc[fn][1] = exp2fast(sAcc[fn][1] - mn0);
            sAcc[fn][2] = exp2fast(sAcc[fn][2] - mn1);
            sAcc[fn][3] = exp2fast(sAcc[fn][3] - mn1);
            ls0 += sAcc[fn][0] + sAcc[fn][1];
            ls1 += sAcc[fn][2] + sAcc[fn][3];
        }
        ls0 += __shfl_xor_sync(0xffffffffu, ls0, 1);
        ls0 += __shfl_xor_sync(0xffffffffu, ls0, 2);
        ls1 += __shfl_xor_sync(0xffffffffu, ls1, 1);
        ls1 += __shfl_xor_sync(0xffffffffu, ls1, 2);
        lrow[0] = lrow[0] * al0 + ls0;
        lrow[1] = lrow[1] * al1 + ls1;
#pragma unroll
        for (int fn = 0; fn < 8; fn++) {
            oAcc[fn][0] *= al0; oAcc[fn][1] *= al0;
            oAcc[fn][2] *= al1; oAcc[fn][3] *= al1;
        }

        uint32_t ph[4][4], pl[4][4];
#pragma unroll
        for (int kk = 0; kk < 4; kk++) {
#pragma unroll
            for (int half = 0; half < 2; half++) {
                const float* src = sAcc[2 * kk + half];
                float x0 = src[0], x1 = src[1], x2 = src[2], x3 = src[3];
                uint32_t hA = packbf2(x0, x1);
                uint32_t hB = packbf2(x2, x3);
                __nv_bfloat162 hA2 = *(__nv_bfloat162*)&hA;
                __nv_bfloat162 hB2 = *(__nv_bfloat162*)&hB;
                uint32_t lA = packbf2(x0 - __bfloat162float(hA2.x),
                                      x1 - __bfloat162float(hA2.y));
                uint32_t lB = packbf2(x2 - __bfloat162float(hB2.x),
                                      x3 - __bfloat162float(hB2.y));
                ph[kk][half * 2 + 0] = hA;
                ph[kk][half * 2 + 1] = hB;
                pl[kk][half * 2 + 0] = lA;
                pl[kk][half * 2 + 1] = lB;
            }
        }

#pragma unroll
        for (int kk = 0; kk < 4; kk++) {
#pragma unroll
            for (int p = 0; p < 4; p++) {
                uint32_t off = (uint32_t)(p * 16 + rpart) * 144u
                             + (uint32_t)(kk * 16 + cpart) * 2u;
                uint32_t h0, h1, h2, h3, l0, l1, l2, l3;
                ldmx4(h0, h1, h2, h3, stV + off);
                ldmx4(l0, l1, l2, l3, stV + FL_BUF + off);
                uint32_t bh0[2] = {h0, h2}, bh1[2] = {h1, h3};
                uint32_t bl0[2] = {l0, l2}, bl1[2] = {l1, l3};
                mma_bf16(oAcc[2 * p],     ph[kk], bh0);
                mma_bf16(oAcc[2 * p],     ph[kk], bl0);
                mma_bf16(oAcc[2 * p],     pl[kk], bh0);
                mma_bf16(oAcc[2 * p + 1], ph[kk], bh1);
                mma_bf16(oAcc[2 * p + 1], ph[kk], bl1);
                mma_bf16(oAcc[2 * p + 1], pl[kk], bh1);
            }
        }
    }

    float inv0 = 1.f / lrow[0];
    float inv1 = 1.f / lrow[1];
    int gi0 = i0 + w * 16 + gr;
#pragma unroll
    for (int fn = 0; fn < 8; fn++) {
        int col = h * DH_ + fn * 8 + gc;
        {
            float o0 = oAcc[fn][0] * inv0, o1 = oAcc[fn][1] * inv0;
            uint32_t hi = packbf2(o0, o1);
            __nv_bfloat162 h2 = *(__nv_bfloat162*)&hi;
            uint32_t lo = packbf2(o0 - __bfloat162float(h2.x), o1 - __bfloat162float(h2.y));
            size_t o = ((size_t)b * N_ + gi0) * INNER_ + col;
            *(uint32_t*)&g_ah[o] = hi;
            *(uint32_t*)&g_al[o] = lo;
        }
        {
            float o0 = oAcc[fn][2] * inv1, o1 = oAcc[fn][3] * inv1;
            uint32_t hi = packbf2(o0, o1);
            __nv_bfloat162 h2 = *(__nv_bfloat162*)&hi;
            uint32_t lo = packbf2(o0 - __bfloat162float(h2.x), o1 - __bfloat162float(h2.y));
            size_t o = ((size_t)b * N_ + gi0 + 8) * INNER_ + col;
            *(uint32_t*)&g_ah[o] = hi;
            *(uint32_t*)&g_al[o] = lo;
        }
    }
}

// ---------------------------------------------------------------------------
// Launch
// ---------------------------------------------------------------------------
extern "C" void kernel_launch(void* const* d_in, const int* in_sizes, int n_in,
                              void* d_out, int out_size)
{
    const float* x    = (const float*)d_in[0];
    const float* rotq = (const float*)d_in[1];
    const float* rotk = (const float*)d_in[2];
    const float* xl   = (const float*)d_in[3];
    const float* Wq   = (const float*)d_in[4];
    const float* Wkv  = (const float*)d_in[5];
    const float* Wout = (const float*)d_in[6];
    const float* nkv  = (const float*)d_in[7];

    float* out1 = (float*)d_out;
    float* out2 = out1 + (size_t)B_ * N_ * INNER_;

    void *pq, *pxh, *pxl, *pah, *pal, *pwh, *pwl;
    cudaGetSymbolAddress(&pq, g_q);
    cudaGetSymbolAddress(&pxh, g_xh);
    cudaGetSymbolAddress(&pxl, g_xl);
    cudaGetSymbolAddress(&pah, g_ah);
    cudaGetSymbolAddress(&pal, g_al);
    cudaGetSymbolAddress(&pwh, g_wh);
    cudaGetSymbolAddress(&pwl, g_wl);

    __nv_bfloat16* xh = (__nv_bfloat16*)pxh;
    __nv_bfloat16* xlo = (__nv_bfloat16*)pxl;
    __nv_bfloat16* ah = (__nv_bfloat16*)pah;
    __nv_bfloat16* al = (__nv_bfloat16*)pal;
    __nv_bfloat16* wh = (__nv_bfloat16*)pwh;
    __nv_bfloat16* wl = (__nv_bfloat16*)pwl;

    cudaFuncSetAttribute(gemm_mma3, cudaFuncAttributeMaxDynamicSharedMemorySize, GEMM_SMEM);
    cudaFuncSetAttribute(flash2, cudaFuncAttributeMaxDynamicSharedMemorySize, FL_SMEM);

    // 1) conversions + weight prep (single merged transpose launch)
    {
        size_t n4 = (size_t)B_ * N_ * DIM_ / 4;
        convert_split<<<(unsigned)((n4 + 255) / 256), 256>>>(x, xh, xlo, n4);
    }
    transpose_split_all<<<dim3(128, 32), dim3(32, 8)>>>(Wq, Wkv, Wout);

    // 2) fused q+kv projection (N=3072): q -> g_q; kv -> out2 rows 1..N
    gemm_mma3<<<dim3(3072 / 128, 4096 / 128), 256, GEMM_SMEM>>>(
        xh, xlo, wh, wl, (float*)pq, out2, 0);

    // 3) K/V assembly (reads kv from out2; writes null row)
    assemble_kv2<<<dim3(KVP_ / 64, H_, B_), 256>>>(xl, nkv, rotk, out2);

    // 4) flash attention (Q rotary in-kernel) -> g_ah/g_al
    flash2<<<dim3(32, H_, B_), 128, FL_SMEM>>>(rotq);

    // 5) output projection
    gemm_mma3<<<dim3(1024 / 128, 4096 / 128), 256, GEMM_SMEM>>>(
        ah, al, wh + 3u * (1u << 20), wl + 3u * (1u << 20), out1, nullptr, 1);
}